// round 13
// baseline (speedup 1.0000x reference)
#include <cuda_runtime.h>

#define L 36864
#define HH 192
#define NHASH 4
#define TOT (NHASH*L)        // 147456
#define CHUNK_ 144
#define NCHUNK 256
#define NCODES 512
#define TILE 1024
#define NTILES 144           // TOT / TILE
#define KTILE 24
#define NKT 18               // 432 / KTILE
#define LOG2E 1.4426950408889634f

typedef unsigned long long ull;

// ---------------- scratch ----------------------------------------------------
__device__ __align__(16) float g_xe[L*8];        // raw query embed
__device__ __align__(16) float g_xnu[L*8];       // normalized embed (keys)
__device__ float g_nrm[L];                       // ||embed|| per pixel
__device__ __align__(16) float g_ye[L*32];       // value embed
__device__ int   g_code[TOT];
__device__ int   g_tileHist[NCODES*NTILES];      // [code][tile], atomic, re-zeroed by scanA
__device__ int   g_tileOff[NCODES*NTILES];
__device__ int   g_codeTot[NCODES];
__device__ int   g_sortIdx[TOT];
__device__ int   g_undo[TOT];
__device__ __align__(16) float g_ret[TOT*32];
__device__ float g_bs[TOT];

// ---------------- f32x2 / cp.async helpers -----------------------------------
__device__ __forceinline__ ull ffma2(ull a, ull b, ull c) {
    ull d;
    asm("fma.rn.f32x2 %0, %1, %2, %3;" : "=l"(d) : "l"(a), "l"(b), "l"(c));
    return d;
}
__device__ __forceinline__ ull fadd2(ull a, ull b) {
    ull d;
    asm("add.rn.f32x2 %0, %1, %2;" : "=l"(d) : "l"(a), "l"(b));
    return d;
}
__device__ __forceinline__ ull fmul2(ull a, ull b) {
    ull d;
    asm("mul.rn.f32x2 %0, %1, %2;" : "=l"(d) : "l"(a), "l"(b));
    return d;
}
__device__ __forceinline__ ull pack2(float lo, float hi) {
    ull d;
    asm("mov.b64 %0, {%1, %2};" : "=l"(d)
        : "r"(__float_as_uint(lo)), "r"(__float_as_uint(hi)));
    return d;
}
__device__ __forceinline__ void unpack2(ull v, float& lo, float& hi) {
    unsigned int a, b;
    asm("mov.b64 {%0, %1}, %2;" : "=r"(a), "=r"(b) : "l"(v));
    lo = __uint_as_float(a); hi = __uint_as_float(b);
}
__device__ __forceinline__ float ex2f(float x) {
    float r;
    asm("ex2.approx.f32 %0, %1;" : "=f"(r) : "f"(x));
    return r;
}
__device__ __forceinline__ void cp16(unsigned int dst, const void* src) {
    asm volatile("cp.async.ca.shared.global [%0], [%1], 16;" :: "r"(dst), "l"(src));
}

// ---------------- K1: convs + hashing + norms + histogram --------------------
__global__ void k_embed(const float* __restrict__ x,
                        const float* __restrict__ wm,
                        const float* __restrict__ bm,
                        const float* __restrict__ wa,
                        const float* __restrict__ ba,
                        const float* __restrict__ rot) {
    __shared__ float s_wm[2304];
    __shared__ float s_wa[1024];
    __shared__ __align__(16) float s_rot[2048];  // transposed: [(h*64+i)][f=8]
    __shared__ float s_bm[8];
    __shared__ float s_ba[32];
    __shared__ int   s_h[NCODES];
    int tid = threadIdx.x;
    for (int t = tid; t < 2304; t += 128) s_wm[t] = wm[t];
    for (int t = tid; t < 1024; t += 128) s_wa[t] = wa[t];
    for (int t = tid; t < 2048; t += 128) {
        int f = t >> 8; int rem = t & 255;
        s_rot[rem*8 + f] = rot[t];
    }
    for (int t = tid; t < NCODES; t += 128) s_h[t] = 0;
    if (tid < 8)  s_bm[tid] = bm[tid];
    if (tid < 32) s_ba[tid] = ba[tid];
    __syncthreads();

    int pix = blockIdx.x*128 + tid;
    int py = pix / HH, px = pix - py*HH;
    float am[8], aa[32];
#pragma unroll
    for (int c = 0; c < 8;  c++) am[c] = s_bm[c];
#pragma unroll
    for (int c = 0; c < 32; c++) aa[c] = s_ba[c];

    bool yl = py > 0, yh = py < HH-1, xl = px > 0, xh = px < HH-1;
    for (int ci = 0; ci < 32; ci++) {
        const float* xc = x + ci*L + py*HH + px;
        float v[9];
        v[4] = xc[0];
        v[0] = (yl&&xl) ? xc[-HH-1] : 0.f;
        v[1] = yl        ? xc[-HH]   : 0.f;
        v[2] = (yl&&xh) ? xc[-HH+1] : 0.f;
        v[3] = xl        ? xc[-1]    : 0.f;
        v[5] = xh        ? xc[1]     : 0.f;
        v[6] = (yh&&xl) ? xc[HH-1]  : 0.f;
        v[7] = yh        ? xc[HH]    : 0.f;
        v[8] = (yh&&xh) ? xc[HH+1]  : 0.f;
#pragma unroll
        for (int co = 0; co < 8; co++) {
            const float* w = &s_wm[(co*32+ci)*9];
#pragma unroll
            for (int t = 0; t < 9; t++) am[co] += w[t]*v[t];
        }
        float vc = v[4];
#pragma unroll
        for (int co = 0; co < 32; co++) aa[co] += s_wa[co*32+ci]*vc;
    }
    float nrm2 = 0.f;
#pragma unroll
    for (int c = 0; c < 8; c++) nrm2 += am[c]*am[c];
    float nrm = sqrtf(nrm2);
    float inv = 1.f / fmaxf(nrm, 5e-5f);
    g_nrm[pix] = nrm;
#pragma unroll
    for (int c = 0; c < 8;  c++) {
        g_xe[pix*8+c]  = am[c];
        g_xnu[pix*8+c] = am[c]*inv;
    }
#pragma unroll
    for (int c = 0; c < 32; c++) g_ye[pix*32+c] = aa[c];

    const float4* r4 = (const float4*)s_rot;
    float4 e0 = make_float4(am[0],am[1],am[2],am[3]);
    float4 e1 = make_float4(am[4],am[5],am[6],am[7]);
    for (int h = 0; h < NHASH; h++) {
        float bP = -1e30f, bN = -1e30f; int iP = 0, iN = 0;
        for (int i = 0; i < 64; i++) {
            float4 a = r4[(h*64+i)*2];
            float4 b = r4[(h*64+i)*2+1];
            float r = e0.x*a.x + e0.y*a.y + e0.z*a.z + e0.w*a.w
                    + e1.x*b.x + e1.y*b.y + e1.z*b.z + e1.w*b.w;
            if ( r > bP) { bP =  r; iP = i; }
            if (-r > bN) { bN = -r; iN = i; }
        }
        int code = ((bN > bP) ? (64 + iN) : iP) + h*128;
        g_code[h*L + pix] = code;
        atomicAdd(&s_h[code], 1);
    }
    __syncthreads();
    for (int t = tid; t < NCODES; t += 128) {
        int v = s_h[t];
        if (v) {
            int tile = (t >> 7)*36 + (blockIdx.x >> 3);
            atomicAdd(&g_tileHist[t*NTILES + tile], v);
        }
    }
}

// ---------------- scanA: per-code prefix over tiles (+ re-zero hist) ---------
__global__ void k_scanA() {                            // one warp per code
    int c = blockIdx.x*8 + (threadIdx.x >> 5);
    int lane = threadIdx.x & 31;
    int run = 0;
    for (int base = 0; base < NTILES; base += 32) {
        int t = base + lane;
        int v = 0;
        if (t < NTILES) {
            v = g_tileHist[c*NTILES + t];
            g_tileHist[c*NTILES + t] = 0;
        }
        int incl = v;
#pragma unroll
        for (int o = 1; o < 32; o <<= 1) {
            int u = __shfl_up_sync(0xffffffffu, incl, o);
            if (lane >= o) incl += u;
        }
        if (t < NTILES) g_tileOff[c*NTILES + t] = run + incl - v;
        run += __shfl_sync(0xffffffffu, incl, 31);
    }
    if (lane == 0) g_codeTot[c] = run;
}

// ---------------- scatter (with inline 512-bin global scan) ------------------
__global__ void k_scatter() {                          // 8 warps per tile, stable
    __shared__ int wcnt[8*NCODES];
    __shared__ int s_sc[NCODES];
    int tile = blockIdx.x;
    int tid = threadIdx.x, w = tid >> 5, lane = tid & 31;
    s_sc[tid]       = g_codeTot[tid];
    s_sc[tid + 256] = g_codeTot[tid + 256];
    for (int c = tid; c < 8*NCODES; c += 256) wcnt[c] = 0;
    __syncthreads();
    for (int off = 1; off < NCODES; off <<= 1) {
        int a = (tid        >= off) ? s_sc[tid - off]       : 0;
        int b = (tid + 256  >= off) ? s_sc[tid + 256 - off] : 0;
        __syncthreads();
        s_sc[tid]       += a;
        s_sc[tid + 256] += b;
        __syncthreads();
    }
    int codes[4];
#pragma unroll
    for (int r = 0; r < 4; r++) {
        int p = tile*TILE + w*128 + r*32 + lane;
        int c = codes[r] = g_code[p];
        unsigned mask = __match_any_sync(0xffffffffu, c);
        int leader = __ffs(mask) - 1;
        if (lane == leader) wcnt[w*NCODES + c] += __popc(mask);
        __syncwarp();
    }
    __syncthreads();
    for (int c = tid; c < NCODES; c += 256) {
        int run = ((c == 0) ? 0 : s_sc[c-1]) + g_tileOff[c*NTILES + tile];
#pragma unroll
        for (int ww = 0; ww < 8; ww++) {
            int v = wcnt[ww*NCODES + c];
            wcnt[ww*NCODES + c] = run;
            run += v;
        }
    }
    __syncthreads();
#pragma unroll
    for (int r = 0; r < 4; r++) {
        int p = tile*TILE + w*128 + r*32 + lane;
        int c = codes[r];
        unsigned mask = __match_any_sync(0xffffffffu, c);
        int leader = __ffs(mask) - 1;
        int below  = __popc(mask & ((1u << lane) - 1u));
        int base = 0;
        if (lane == leader) {
            base = wcnt[w*NCODES + c];
            wcnt[w*NCODES + c] = base + __popc(mask);
        }
        base = __shfl_sync(0xffffffffu, base, leader);
        int dest = base + below;
        g_sortIdx[dest] = p;
        g_undo[p] = dest;
        __syncwarp();
    }
}

// ---------------- attention: two-phase, KTILE=24 for 6 blocks/SM -------------
// Keys unit-norm => score s = q.k <= ||q||; m = ||q|| is a valid softmax max.
// Phase A (thread = query): probs for a 24-key tile -> s_p[key][query].
// Phase B (thread = 4 queries x 8 channels): register-tiled P*V GEMM.
// Values double-buffered cp.async; lsum finalized by in-warp shuffles.
__global__ __launch_bounds__(160, 6) void k_attn() {
    __shared__ int  s_l[432];                        // 1728 B
    __shared__ __align__(16) ull   s_kp[216*8];      // packed key pairs (13824 B)
    __shared__ __align__(16) float s_p[KTILE*144];   // prob tile [key][query] (13824 B)
    __shared__ __align__(16) ull   s_y[2][KTILE*16]; // value tiles (6144 B)
    int blk = blockIdx.x;
    int h = blk >> 8, k = blk & 255;
    int tid = threadIdx.x;
    int hb = h*L;
    int kb1 = (k + 255) & 255, kb2 = (k + 1) & 255;
    int baseQ = hb + k*CHUNK_;
    int sb0 = baseQ, sb1 = hb + kb1*CHUNK_, sb2 = hb + kb2*CHUNK_;

    for (int e = tid; e < 432; e += 160) {
        int seg = e / CHUNK_; int r = e - seg*CHUNK_;
        int sb = (seg == 0) ? sb0 : ((seg == 1) ? sb1 : sb2);
        s_l[e] = g_sortIdx[sb + r] % L;
    }
    __syncthreads();

    unsigned int ybase = (unsigned int)__cvta_generic_to_shared(&s_y[0][0]);
    auto stage = [&](int t) {                        // value tile t -> buffer t&1
        unsigned int vd = ybase + (unsigned int)(t & 1) * (KTILE*128u);
        int base = t*KTILE;
        for (int e = tid; e < KTILE*8; e += 160) {
            int jr = e >> 3, ch = e & 7;
            cp16(vd + e*16u, g_ye + (size_t)s_l[base + jr]*32 + ch*4);
        }
        asm volatile("cp.async.commit_group;" ::: "memory");
    };
    stage(0);

    // pack key pairs: s_kp[jp*8+d] = (k[2jp][d], k[2jp+1][d])
    for (int e = tid; e < 1728; e += 160) {
        int jp = e >> 3, d = e & 7;
        s_kp[e] = pack2(g_xnu[(size_t)s_l[2*jp]*8 + d], g_xnu[(size_t)s_l[2*jp+1]*8 + d]);
    }

    ull qq[8];
    ull acc[16];
    float m = 0.f, m2 = 0.f, lsum = 0.f;
    if (tid < CHUNK_) {
        int lq = s_l[tid];
        m = g_nrm[lq];
        m2 = m * LOG2E;
        const float* qp = g_xe + (size_t)lq*8;
#pragma unroll
        for (int d = 0; d < 8; d++) {
            float qv = qp[d] * LOG2E;                // log2-domain queries
            qq[d] = pack2(qv, qv);
        }
    }
#pragma unroll
    for (int q = 0; q < 16; q++) acc[q] = 0ull;
    int qg = tid >> 2, cg = tid & 3;                 // phase-B mapping (tid<144)
    int lgrp = (tid & 31) & ~3;                      // aligned 4-lane group base
    __syncthreads();                                 // s_kp ready

    for (int t = 0; t < NKT; t++) {
        if (t + 1 < NKT) stage(t + 1);
        // ---- phase A: scores(log2) -> probs -> s_p (overlaps value copy) ----
        if (tid < CHUNK_) {
#pragma unroll 3
            for (int jp = 0; jp < KTILE/2; jp++) {
                const ulonglong2* kp = (const ulonglong2*)&s_kp[(t*(KTILE/2) + jp)*8];
                ulonglong2 k01 = kp[0], k23 = kp[1];
                ulonglong2 k45 = kp[2], k67 = kp[3];
                ull sa = ffma2(qq[0], k01.x, 0ull);  // two independent chains
                ull sb = ffma2(qq[1], k01.y, 0ull);
                sa = ffma2(qq[2], k23.x, sa);
                sb = ffma2(qq[3], k23.y, sb);
                sa = ffma2(qq[4], k45.x, sa);
                sb = ffma2(qq[5], k45.y, sb);
                sa = ffma2(qq[6], k67.x, sa);
                sb = ffma2(qq[7], k67.y, sb);
                ull sp = fadd2(sa, sb);
                float lo, hi; unpack2(sp, lo, hi);
                float p0 = ex2f(lo - m2);
                float p1 = ex2f(hi - m2);
                lsum += p0 + p1;
                s_p[(2*jp)*144 + tid]   = p0;
                s_p[(2*jp+1)*144 + tid] = p1;
            }
        }
        if (t + 1 < NKT) { asm volatile("cp.async.wait_group 1;" ::: "memory"); }
        else             { asm volatile("cp.async.wait_group 0;" ::: "memory"); }
        __syncthreads();                             // s_p + value tile t ready
        // ---- phase B: register-tiled P x V ----
        const ull* yb = s_y[t & 1];
        if (tid < CHUNK_) {
#pragma unroll 4
            for (int j = 0; j < KTILE; j++) {
                float4 pv = *(const float4*)&s_p[j*144 + 4*qg];
                const ulonglong2* vr = (const ulonglong2*)&yb[j*16 + cg*4];
                ulonglong2 v0 = vr[0], v1 = vr[1];
                ull pp;
                pp = pack2(pv.x, pv.x);
                acc[0]  = ffma2(pp, v0.x, acc[0]);  acc[1]  = ffma2(pp, v0.y, acc[1]);
                acc[2]  = ffma2(pp, v1.x, acc[2]);  acc[3]  = ffma2(pp, v1.y, acc[3]);
                pp = pack2(pv.y, pv.y);
                acc[4]  = ffma2(pp, v0.x, acc[4]);  acc[5]  = ffma2(pp, v0.y, acc[5]);
                acc[6]  = ffma2(pp, v1.x, acc[6]);  acc[7]  = ffma2(pp, v1.y, acc[7]);
                pp = pack2(pv.z, pv.z);
                acc[8]  = ffma2(pp, v0.x, acc[8]);  acc[9]  = ffma2(pp, v0.y, acc[9]);
                acc[10] = ffma2(pp, v1.x, acc[10]); acc[11] = ffma2(pp, v1.y, acc[11]);
                pp = pack2(pv.w, pv.w);
                acc[12] = ffma2(pp, v0.x, acc[12]); acc[13] = ffma2(pp, v0.y, acc[13]);
                acc[14] = ffma2(pp, v1.x, acc[14]); acc[15] = ffma2(pp, v1.y, acc[15]);
            }
        }
        __syncthreads();                             // protect s_p + value buffer
    }

    // final lsum for the 4 queries of this thread's group: in-warp shuffle
    float ls0 = __shfl_sync(0xffffffffu, lsum, lgrp + 0);
    float ls1 = __shfl_sync(0xffffffffu, lsum, lgrp + 1);
    float ls2 = __shfl_sync(0xffffffffu, lsum, lgrp + 2);
    float ls3 = __shfl_sync(0xffffffffu, lsum, lgrp + 3);
    if (tid < CHUNK_) {
        g_bs[baseQ + tid] = m + __logf(lsum);
        float lsq[4] = {ls0, ls1, ls2, ls3};
#pragma unroll
        for (int q = 0; q < 4; q++) {
            float inv = 1.f / lsq[q];
            ull inv2 = pack2(inv, inv);
            int row = baseQ + 4*qg + q;
            ull* o = ((ull*)g_ret) + (size_t)row*16 + cg*4;
            o[0] = fmul2(acc[4*q+0], inv2);
            o[1] = fmul2(acc[4*q+1], inv2);
            o[2] = fmul2(acc[4*q+2], inv2);
            o[3] = fmul2(acc[4*q+3], inv2);
        }
    }
}

// ---------------- un-sort + cross-hash softmax + residual --------------------
__global__ void k_combine(const float* __restrict__ x, float* __restrict__ out) {
    __shared__ int   s_d[4][32];
    __shared__ float s_p[4][32];
    int tx = threadIdx.x, c = threadIdx.y;
    int l = blockIdx.x*32 + tx;
    if (c < 4) {
        int d = g_undo[c*L + l];
        s_d[c][tx] = d;
        s_p[c][tx] = g_bs[d];
    }
    __syncthreads();
    if (c == 0) {
        float b0 = s_p[0][tx], b1 = s_p[1][tx], b2 = s_p[2][tx], b3 = s_p[3][tx];
        float mm = fmaxf(fmaxf(b0,b1), fmaxf(b2,b3));
        float e0 = __expf(b0-mm), e1 = __expf(b1-mm), e2 = __expf(b2-mm), e3 = __expf(b3-mm);
        float inv = 1.f/(e0+e1+e2+e3);
        s_p[0][tx] = e0*inv; s_p[1][tx] = e1*inv; s_p[2][tx] = e2*inv; s_p[3][tx] = e3*inv;
    }
    __syncthreads();
    float sum = 0.f;
#pragma unroll
    for (int h = 0; h < 4; h++)
        sum += s_p[h][tx] * g_ret[(size_t)s_d[h][tx]*32 + c];
    out[c*L + l] = sum + x[c*L + l];
}

// ---------------- launcher ---------------------------------------------------
extern "C" void kernel_launch(void* const* d_in, const int* in_sizes, int n_in,
                              void* d_out, int out_size) {
    const float* x   = (const float*)d_in[0];
    const float* wm  = (const float*)d_in[1];
    const float* bm  = (const float*)d_in[2];
    const float* wa  = (const float*)d_in[3];
    const float* ba  = (const float*)d_in[4];
    const float* rot = (const float*)d_in[5];
    float* out = (float*)d_out;

    k_embed<<<L/128, 128>>>(x, wm, bm, wa, ba, rot);
    k_scanA<<<64, 256>>>();
    k_scatter<<<NTILES, 256>>>();
    k_attn<<<NHASH*NCHUNK, 160>>>();                 // 4th launch -> profiled
    k_combine<<<L/32, dim3(32,32)>>>(x, out);
}

// round 14
// speedup vs baseline: 1.0443x; 1.0443x over previous
#include <cuda_runtime.h>

#define L 36864
#define HH 192
#define NHASH 4
#define TOT (NHASH*L)        // 147456
#define CHUNK_ 144
#define NCHUNK 256
#define NCODES 512
#define TILE 1024
#define NTILES 144           // TOT / TILE
#define KTILE 36
#define NKT 12               // 432 / KTILE
#define LOG2E 1.4426950408889634f

typedef unsigned long long ull;

// ---------------- scratch ----------------------------------------------------
__device__ __align__(16) float g_xe[L*8];        // raw query embed
__device__ __align__(16) float g_xnu[L*8];       // normalized embed (keys)
__device__ float g_nrm[L];                       // ||embed|| per pixel
__device__ __align__(16) float g_ye[L*32];       // value embed
__device__ int   g_code[TOT];
__device__ int   g_tileHist[NCODES*NTILES];      // [code][tile], atomic, re-zeroed by scanA
__device__ int   g_tileOff[NCODES*NTILES];
__device__ int   g_codeTot[NCODES];
__device__ int   g_sortIdx[TOT];
__device__ int   g_undo[TOT];
__device__ __align__(16) float g_ret[TOT*32];
__device__ float g_bs[TOT];

// ---------------- f32x2 / cp.async helpers -----------------------------------
__device__ __forceinline__ ull ffma2(ull a, ull b, ull c) {
    ull d;
    asm("fma.rn.f32x2 %0, %1, %2, %3;" : "=l"(d) : "l"(a), "l"(b), "l"(c));
    return d;
}
__device__ __forceinline__ ull fadd2(ull a, ull b) {
    ull d;
    asm("add.rn.f32x2 %0, %1, %2;" : "=l"(d) : "l"(a), "l"(b));
    return d;
}
__device__ __forceinline__ ull fmul2(ull a, ull b) {
    ull d;
    asm("mul.rn.f32x2 %0, %1, %2;" : "=l"(d) : "l"(a), "l"(b));
    return d;
}
__device__ __forceinline__ ull pack2(float lo, float hi) {
    ull d;
    asm("mov.b64 %0, {%1, %2};" : "=l"(d)
        : "r"(__float_as_uint(lo)), "r"(__float_as_uint(hi)));
    return d;
}
__device__ __forceinline__ void unpack2(ull v, float& lo, float& hi) {
    unsigned int a, b;
    asm("mov.b64 {%0, %1}, %2;" : "=r"(a), "=r"(b) : "l"(v));
    lo = __uint_as_float(a); hi = __uint_as_float(b);
}
__device__ __forceinline__ float ex2f(float x) {
    float r;
    asm("ex2.approx.f32 %0, %1;" : "=f"(r) : "f"(x));
    return r;
}
__device__ __forceinline__ void cp16(unsigned int dst, const void* src) {
    asm volatile("cp.async.ca.shared.global [%0], [%1], 16;" :: "r"(dst), "l"(src));
}

// ---------------- K1: convs + hashing + norms + histogram --------------------
__global__ void k_embed(const float* __restrict__ x,
                        const float* __restrict__ wm,
                        const float* __restrict__ bm,
                        const float* __restrict__ wa,
                        const float* __restrict__ ba,
                        const float* __restrict__ rot) {
    __shared__ float s_wm[2304];
    __shared__ float s_wa[1024];
    __shared__ __align__(16) float s_rot[2048];  // transposed: [(h*64+i)][f=8]
    __shared__ float s_bm[8];
    __shared__ float s_ba[32];
    __shared__ int   s_h[NCODES];
    int tid = threadIdx.x;
    for (int t = tid; t < 2304; t += 128) s_wm[t] = wm[t];
    for (int t = tid; t < 1024; t += 128) s_wa[t] = wa[t];
    for (int t = tid; t < 2048; t += 128) {
        int f = t >> 8; int rem = t & 255;
        s_rot[rem*8 + f] = rot[t];
    }
    for (int t = tid; t < NCODES; t += 128) s_h[t] = 0;
    if (tid < 8)  s_bm[tid] = bm[tid];
    if (tid < 32) s_ba[tid] = ba[tid];
    __syncthreads();

    int pix = blockIdx.x*128 + tid;
    int py = pix / HH, px = pix - py*HH;
    float am[8], aa[32];
#pragma unroll
    for (int c = 0; c < 8;  c++) am[c] = s_bm[c];
#pragma unroll
    for (int c = 0; c < 32; c++) aa[c] = s_ba[c];

    bool yl = py > 0, yh = py < HH-1, xl = px > 0, xh = px < HH-1;
    for (int ci = 0; ci < 32; ci++) {
        const float* xc = x + ci*L + py*HH + px;
        float v[9];
        v[4] = xc[0];
        v[0] = (yl&&xl) ? xc[-HH-1] : 0.f;
        v[1] = yl        ? xc[-HH]   : 0.f;
        v[2] = (yl&&xh) ? xc[-HH+1] : 0.f;
        v[3] = xl        ? xc[-1]    : 0.f;
        v[5] = xh        ? xc[1]     : 0.f;
        v[6] = (yh&&xl) ? xc[HH-1]  : 0.f;
        v[7] = yh        ? xc[HH]    : 0.f;
        v[8] = (yh&&xh) ? xc[HH+1]  : 0.f;
#pragma unroll
        for (int co = 0; co < 8; co++) {
            const float* w = &s_wm[(co*32+ci)*9];
#pragma unroll
            for (int t = 0; t < 9; t++) am[co] += w[t]*v[t];
        }
        float vc = v[4];
#pragma unroll
        for (int co = 0; co < 32; co++) aa[co] += s_wa[co*32+ci]*vc;
    }
    float nrm2 = 0.f;
#pragma unroll
    for (int c = 0; c < 8; c++) nrm2 += am[c]*am[c];
    float nrm = sqrtf(nrm2);
    float inv = 1.f / fmaxf(nrm, 5e-5f);
    g_nrm[pix] = nrm;
#pragma unroll
    for (int c = 0; c < 8;  c++) {
        g_xe[pix*8+c]  = am[c];
        g_xnu[pix*8+c] = am[c]*inv;
    }
#pragma unroll
    for (int c = 0; c < 32; c++) g_ye[pix*32+c] = aa[c];

    const float4* r4 = (const float4*)s_rot;
    float4 e0 = make_float4(am[0],am[1],am[2],am[3]);
    float4 e1 = make_float4(am[4],am[5],am[6],am[7]);
    for (int h = 0; h < NHASH; h++) {
        float bP = -1e30f, bN = -1e30f; int iP = 0, iN = 0;
        for (int i = 0; i < 64; i++) {
            float4 a = r4[(h*64+i)*2];
            float4 b = r4[(h*64+i)*2+1];
            float r = e0.x*a.x + e0.y*a.y + e0.z*a.z + e0.w*a.w
                    + e1.x*b.x + e1.y*b.y + e1.z*b.z + e1.w*b.w;
            if ( r > bP) { bP =  r; iP = i; }
            if (-r > bN) { bN = -r; iN = i; }
        }
        int code = ((bN > bP) ? (64 + iN) : iP) + h*128;
        g_code[h*L + pix] = code;
        atomicAdd(&s_h[code], 1);
    }
    __syncthreads();
    for (int t = tid; t < NCODES; t += 128) {
        int v = s_h[t];
        if (v) {
            int tile = (t >> 7)*36 + (blockIdx.x >> 3);
            atomicAdd(&g_tileHist[t*NTILES + tile], v);
        }
    }
}

// ---------------- scanA: per-code prefix over tiles (+ re-zero hist) ---------
__global__ void k_scanA() {                            // one warp per code
    int c = blockIdx.x*8 + (threadIdx.x >> 5);
    int lane = threadIdx.x & 31;
    int run = 0;
    for (int base = 0; base < NTILES; base += 32) {
        int t = base + lane;
        int v = 0;
        if (t < NTILES) {
            v = g_tileHist[c*NTILES + t];
            g_tileHist[c*NTILES + t] = 0;
        }
        int incl = v;
#pragma unroll
        for (int o = 1; o < 32; o <<= 1) {
            int u = __shfl_up_sync(0xffffffffu, incl, o);
            if (lane >= o) incl += u;
        }
        if (t < NTILES) g_tileOff[c*NTILES + t] = run + incl - v;
        run += __shfl_sync(0xffffffffu, incl, 31);
    }
    if (lane == 0) g_codeTot[c] = run;
}

// ---------------- scatter (with inline 512-bin global scan) ------------------
__global__ void k_scatter() {                          // 8 warps per tile, stable
    __shared__ int wcnt[8*NCODES];
    __shared__ int s_sc[NCODES];
    int tile = blockIdx.x;
    int tid = threadIdx.x, w = tid >> 5, lane = tid & 31;
    s_sc[tid]       = g_codeTot[tid];
    s_sc[tid + 256] = g_codeTot[tid + 256];
    for (int c = tid; c < 8*NCODES; c += 256) wcnt[c] = 0;
    __syncthreads();
    for (int off = 1; off < NCODES; off <<= 1) {
        int a = (tid        >= off) ? s_sc[tid - off]       : 0;
        int b = (tid + 256  >= off) ? s_sc[tid + 256 - off] : 0;
        __syncthreads();
        s_sc[tid]       += a;
        s_sc[tid + 256] += b;
        __syncthreads();
    }
    int codes[4];
#pragma unroll
    for (int r = 0; r < 4; r++) {
        int p = tile*TILE + w*128 + r*32 + lane;
        int c = codes[r] = g_code[p];
        unsigned mask = __match_any_sync(0xffffffffu, c);
        int leader = __ffs(mask) - 1;
        if (lane == leader) wcnt[w*NCODES + c] += __popc(mask);
        __syncwarp();
    }
    __syncthreads();
    for (int c = tid; c < NCODES; c += 256) {
        int run = ((c == 0) ? 0 : s_sc[c-1]) + g_tileOff[c*NTILES + tile];
#pragma unroll
        for (int ww = 0; ww < 8; ww++) {
            int v = wcnt[ww*NCODES + c];
            wcnt[ww*NCODES + c] = run;
            run += v;
        }
    }
    __syncthreads();
#pragma unroll
    for (int r = 0; r < 4; r++) {
        int p = tile*TILE + w*128 + r*32 + lane;
        int c = codes[r];
        unsigned mask = __match_any_sync(0xffffffffu, c);
        int leader = __ffs(mask) - 1;
        int below  = __popc(mask & ((1u << lane) - 1u));
        int base = 0;
        if (lane == leader) {
            base = wcnt[w*NCODES + c];
            wcnt[w*NCODES + c] = base + __popc(mask);
        }
        base = __shfl_sync(0xffffffffu, base, leader);
        int dest = base + below;
        g_sortIdx[dest] = p;
        g_undo[p] = dest;
        __syncwarp();
    }
}

// ---------------- attention: two-phase + ex2 + bias-folded chains ------------
// Keys unit-norm => score s = q.k <= ||q||; m = ||q|| is a valid softmax max.
// Phase A (thread = query): probs for a 36-key tile -> s_p[key][query].
//   Scores in log2 domain; the -m2 bias is folded into the FFMA2 chain init,
//   so ex2 consumes the chain output directly (no per-key subtract).
// Phase B (thread = 4 queries x 8 channels): register-tiled P*V GEMM.
// Values double-buffered cp.async; lsum finalized by in-warp shuffles.
__global__ __launch_bounds__(160, 5) void k_attn() {
    __shared__ int  s_l[432];                        // 1728 B
    __shared__ __align__(16) ull   s_kp[216*8];      // packed key pairs (13824 B)
    __shared__ __align__(16) float s_p[KTILE*144];   // prob tile [key][query] (20736 B)
    __shared__ __align__(16) ull   s_y[2][KTILE*16]; // value tiles (9216 B)
    int blk = blockIdx.x;
    int h = blk >> 8, k = blk & 255;
    int tid = threadIdx.x;
    int hb = h*L;
    int kb1 = (k + 255) & 255, kb2 = (k + 1) & 255;
    int baseQ = hb + k*CHUNK_;
    int sb0 = baseQ, sb1 = hb + kb1*CHUNK_, sb2 = hb + kb2*CHUNK_;

    for (int e = tid; e < 432; e += 160) {
        int seg = e / CHUNK_; int r = e - seg*CHUNK_;
        int sb = (seg == 0) ? sb0 : ((seg == 1) ? sb1 : sb2);
        s_l[e] = g_sortIdx[sb + r] % L;
    }
    __syncthreads();

    unsigned int ybase = (unsigned int)__cvta_generic_to_shared(&s_y[0][0]);
    auto stage = [&](int t) {                        // value tile t -> buffer t&1
        unsigned int vd = ybase + (unsigned int)(t & 1) * (KTILE*128u);
        int base = t*KTILE;
        for (int e = tid; e < KTILE*8; e += 160) {
            int jr = e >> 3, ch = e & 7;
            cp16(vd + e*16u, g_ye + (size_t)s_l[base + jr]*32 + ch*4);
        }
        asm volatile("cp.async.commit_group;" ::: "memory");
    };
    stage(0);

    // pack key pairs: s_kp[jp*8+d] = (k[2jp][d], k[2jp+1][d])
    for (int e = tid; e < 1728; e += 160) {
        int jp = e >> 3, d = e & 7;
        s_kp[e] = pack2(g_xnu[(size_t)s_l[2*jp]*8 + d], g_xnu[(size_t)s_l[2*jp+1]*8 + d]);
    }

    ull qq[8];
    ull acc[16];
    ull bias2 = 0ull;
    float m = 0.f, lsum = 0.f;
    if (tid < CHUNK_) {
        int lq = s_l[tid];
        m = g_nrm[lq];
        float m2 = m * LOG2E;
        bias2 = pack2(-m2, -m2);                     // folded softmax bias
        const float* qp = g_xe + (size_t)lq*8;
#pragma unroll
        for (int d = 0; d < 8; d++) {
            float qv = qp[d] * LOG2E;                // log2-domain queries
            qq[d] = pack2(qv, qv);
        }
    }
#pragma unroll
    for (int q = 0; q < 16; q++) acc[q] = 0ull;
    int qg = tid >> 2, cg = tid & 3;                 // phase-B mapping (tid<144)
    int lgrp = (tid & 31) & ~3;                      // aligned 4-lane group base
    __syncthreads();                                 // s_kp ready

    for (int t = 0; t < NKT; t++) {
        if (t + 1 < NKT) stage(t + 1);
        // ---- phase A: scores(log2, bias-folded) -> probs -> s_p -------------
        if (tid < CHUNK_) {
#pragma unroll 3
            for (int jp = 0; jp < KTILE/2; jp++) {
                const ulonglong2* kp = (const ulonglong2*)&s_kp[(t*(KTILE/2) + jp)*8];
                ulonglong2 k01 = kp[0], k23 = kp[1];
                ulonglong2 k45 = kp[2], k67 = kp[3];
                ull sa = ffma2(qq[0], k01.x, bias2); // bias folded into chain init
                ull sb = ffma2(qq[1], k01.y, 0ull);
                sa = ffma2(qq[2], k23.x, sa);
                sb = ffma2(qq[3], k23.y, sb);
                sa = ffma2(qq[4], k45.x, sa);
                sb = ffma2(qq[5], k45.y, sb);
                sa = ffma2(qq[6], k67.x, sa);
                sb = ffma2(qq[7], k67.y, sb);
                ull sp = fadd2(sa, sb);
                float lo, hi; unpack2(sp, lo, hi);
                float p0 = ex2f(lo);
                float p1 = ex2f(hi);
                lsum += p0 + p1;
                s_p[(2*jp)*144 + tid]   = p0;
                s_p[(2*jp+1)*144 + tid] = p1;
            }
        }
        if (t + 1 < NKT) { asm volatile("cp.async.wait_group 1;" ::: "memory"); }
        else             { asm volatile("cp.async.wait_group 0;" ::: "memory"); }
        __syncthreads();                             // s_p + value tile t ready
        // ---- phase B: register-tiled P x V ----
        const ull* yb = s_y[t & 1];
        if (tid < CHUNK_) {
#pragma unroll 4
            for (int j = 0; j < KTILE; j++) {
                float4 pv = *(const float4*)&s_p[j*144 + 4*qg];
                const ulonglong2* vr = (const ulonglong2*)&yb[j*16 + cg*4];
                ulonglong2 v0 = vr[0], v1 = vr[1];
                ull pp;
                pp = pack2(pv.x, pv.x);
                acc[0]  = ffma2(pp, v0.x, acc[0]);  acc[1]  = ffma2(pp, v0.y, acc[1]);
                acc[2]  = ffma2(pp, v1.x, acc[2]);  acc[3]  = ffma2(pp, v1.y, acc[3]);
                pp = pack2(pv.y, pv.y);
                acc[4]  = ffma2(pp, v0.x, acc[4]);  acc[5]  = ffma2(pp, v0.y, acc[5]);
                acc[6]  = ffma2(pp, v1.x, acc[6]);  acc[7]  = ffma2(pp, v1.y, acc[7]);
                pp = pack2(pv.z, pv.z);
                acc[8]  = ffma2(pp, v0.x, acc[8]);  acc[9]  = ffma2(pp, v0.y, acc[9]);
                acc[10] = ffma2(pp, v1.x, acc[10]); acc[11] = ffma2(pp, v1.y, acc[11]);
                pp = pack2(pv.w, pv.w);
                acc[12] = ffma2(pp, v0.x, acc[12]); acc[13] = ffma2(pp, v0.y, acc[13]);
                acc[14] = ffma2(pp, v1.x, acc[14]); acc[15] = ffma2(pp, v1.y, acc[15]);
            }
        }
        __syncthreads();                             // protect s_p + value buffer
    }

    // final lsum for the 4 queries of this thread's group: in-warp shuffle
    float ls0 = __shfl_sync(0xffffffffu, lsum, lgrp + 0);
    float ls1 = __shfl_sync(0xffffffffu, lsum, lgrp + 1);
    float ls2 = __shfl_sync(0xffffffffu, lsum, lgrp + 2);
    float ls3 = __shfl_sync(0xffffffffu, lsum, lgrp + 3);
    if (tid < CHUNK_) {
        g_bs[baseQ + tid] = m + __logf(lsum);
        float lsq[4] = {ls0, ls1, ls2, ls3};
#pragma unroll
        for (int q = 0; q < 4; q++) {
            float inv = 1.f / lsq[q];
            ull inv2 = pack2(inv, inv);
            int row = baseQ + 4*qg + q;
            ull* o = ((ull*)g_ret) + (size_t)row*16 + cg*4;
            o[0] = fmul2(acc[4*q+0], inv2);
            o[1] = fmul2(acc[4*q+1], inv2);
            o[2] = fmul2(acc[4*q+2], inv2);
            o[3] = fmul2(acc[4*q+3], inv2);
        }
    }
}

// ---------------- un-sort + cross-hash softmax + residual --------------------
__global__ void k_combine(const float* __restrict__ x, float* __restrict__ out) {
    __shared__ int   s_d[4][32];
    __shared__ float s_p[4][32];
    int tx = threadIdx.x, c = threadIdx.y;
    int l = blockIdx.x*32 + tx;
    if (c < 4) {
        int d = g_undo[c*L + l];
        s_d[c][tx] = d;
        s_p[c][tx] = g_bs[d];
    }
    __syncthreads();
    if (c == 0) {
        float b0 = s_p[0][tx], b1 = s_p[1][tx], b2 = s_p[2][tx], b3 = s_p[3][tx];
        float mm = fmaxf(fmaxf(b0,b1), fmaxf(b2,b3));
        float e0 = __expf(b0-mm), e1 = __expf(b1-mm), e2 = __expf(b2-mm), e3 = __expf(b3-mm);
        float inv = 1.f/(e0+e1+e2+e3);
        s_p[0][tx] = e0*inv; s_p[1][tx] = e1*inv; s_p[2][tx] = e2*inv; s_p[3][tx] = e3*inv;
    }
    __syncthreads();
    float sum = 0.f;
#pragma unroll
    for (int h = 0; h < 4; h++)
        sum += s_p[h][tx] * g_ret[(size_t)s_d[h][tx]*32 + c];
    out[c*L + l] = sum + x[c*L + l];
}

// ---------------- launcher ---------------------------------------------------
extern "C" void kernel_launch(void* const* d_in, const int* in_sizes, int n_in,
                              void* d_out, int out_size) {
    const float* x   = (const float*)d_in[0];
    const float* wm  = (const float*)d_in[1];
    const float* bm  = (const float*)d_in[2];
    const float* wa  = (const float*)d_in[3];
    const float* ba  = (const float*)d_in[4];
    const float* rot = (const float*)d_in[5];
    float* out = (float*)d_out;

    k_embed<<<L/128, 128>>>(x, wm, bm, wa, ba, rot);
    k_scanA<<<64, 256>>>();
    k_scatter<<<NTILES, 256>>>();
    k_attn<<<NHASH*NCHUNK, 160>>>();                 // 4th launch -> profiled
    k_combine<<<L/32, dim3(32,32)>>>(x, out);
}

// round 15
// speedup vs baseline: 1.0554x; 1.0106x over previous
#include <cuda_runtime.h>

#define L 36864
#define HH 192
#define NHASH 4
#define TOT (NHASH*L)        // 147456
#define CHUNK_ 144
#define NCHUNK 256
#define NCODES 512
#define TILE 1024
#define NTILES 144           // TOT / TILE
#define KTILE 48
#define NKT 9                // 432 / KTILE
#define SPS 152              // s_p row stride (floats), bank-conflict-free
#define SYS 40               // s_y row stride (floats), bank-conflict-free
#define LOG2E 1.4426950408889634f

typedef unsigned long long ull;

// ---------------- scratch ----------------------------------------------------
__device__ __align__(16) float g_xe[L*8];        // raw query embed
__device__ __align__(16) float g_xnu[L*8];       // normalized embed (keys)
__device__ float g_nrm[L];                       // ||embed|| per pixel
__device__ __align__(16) float g_ye[L*32];       // value embed
__device__ int   g_code[TOT];
__device__ int   g_tileHist[NCODES*NTILES];      // [code][tile], atomic, re-zeroed by scanA
__device__ int   g_tileOff[NCODES*NTILES];
__device__ int   g_codeTot[NCODES];
__device__ int   g_sortIdx[TOT];
__device__ int   g_undo[TOT];
__device__ __align__(16) float g_ret[TOT*32];
__device__ float g_bs[TOT];

// ---------------- f32x2 / cp.async / mma helpers -----------------------------
__device__ __forceinline__ ull ffma2(ull a, ull b, ull c) {
    ull d;
    asm("fma.rn.f32x2 %0, %1, %2, %3;" : "=l"(d) : "l"(a), "l"(b), "l"(c));
    return d;
}
__device__ __forceinline__ ull fadd2(ull a, ull b) {
    ull d;
    asm("add.rn.f32x2 %0, %1, %2;" : "=l"(d) : "l"(a), "l"(b));
    return d;
}
__device__ __forceinline__ ull pack2(float lo, float hi) {
    ull d;
    asm("mov.b64 %0, {%1, %2};" : "=l"(d)
        : "r"(__float_as_uint(lo)), "r"(__float_as_uint(hi)));
    return d;
}
__device__ __forceinline__ void unpack2(ull v, float& lo, float& hi) {
    unsigned int a, b;
    asm("mov.b64 {%0, %1}, %2;" : "=r"(a), "=r"(b) : "l"(v));
    lo = __uint_as_float(a); hi = __uint_as_float(b);
}
__device__ __forceinline__ float ex2f(float x) {
    float r;
    asm("ex2.approx.f32 %0, %1;" : "=f"(r) : "f"(x));
    return r;
}
__device__ __forceinline__ void cp16(unsigned int dst, const void* src) {
    asm volatile("cp.async.ca.shared.global [%0], [%1], 16;" :: "r"(dst), "l"(src));
}
// m16n8k4 tf32 mma: D += A(16x4) * B(4x8); A={a0:(g,t),a1:(g+8,t)}, B={b0:(t,g)}
#define MMA4(D, A0, A1, B0) \
    asm volatile("mma.sync.aligned.m16n8k4.row.col.f32.tf32.tf32.f32 " \
        "{%0,%1,%2,%3}, {%4,%5}, {%6}, {%0,%1,%2,%3};" \
        : "+f"((D)[0]), "+f"((D)[1]), "+f"((D)[2]), "+f"((D)[3]) \
        : "r"(A0), "r"(A1), "r"(B0))

// ---------------- K1: convs + hashing + norms + histogram --------------------
__global__ void k_embed(const float* __restrict__ x,
                        const float* __restrict__ wm,
                        const float* __restrict__ bm,
                        const float* __restrict__ wa,
                        const float* __restrict__ ba,
                        const float* __restrict__ rot) {
    __shared__ float s_wm[2304];
    __shared__ float s_wa[1024];
    __shared__ __align__(16) float s_rot[2048];  // transposed: [(h*64+i)][f=8]
    __shared__ float s_bm[8];
    __shared__ float s_ba[32];
    __shared__ int   s_h[NCODES];
    int tid = threadIdx.x;
    for (int t = tid; t < 2304; t += 128) s_wm[t] = wm[t];
    for (int t = tid; t < 1024; t += 128) s_wa[t] = wa[t];
    for (int t = tid; t < 2048; t += 128) {
        int f = t >> 8; int rem = t & 255;
        s_rot[rem*8 + f] = rot[t];
    }
    for (int t = tid; t < NCODES; t += 128) s_h[t] = 0;
    if (tid < 8)  s_bm[tid] = bm[tid];
    if (tid < 32) s_ba[tid] = ba[tid];
    __syncthreads();

    int pix = blockIdx.x*128 + tid;
    int py = pix / HH, px = pix - py*HH;
    float am[8], aa[32];
#pragma unroll
    for (int c = 0; c < 8;  c++) am[c] = s_bm[c];
#pragma unroll
    for (int c = 0; c < 32; c++) aa[c] = s_ba[c];

    bool yl = py > 0, yh = py < HH-1, xl = px > 0, xh = px < HH-1;
    for (int ci = 0; ci < 32; ci++) {
        const float* xc = x + ci*L + py*HH + px;
        float v[9];
        v[4] = xc[0];
        v[0] = (yl&&xl) ? xc[-HH-1] : 0.f;
        v[1] = yl        ? xc[-HH]   : 0.f;
        v[2] = (yl&&xh) ? xc[-HH+1] : 0.f;
        v[3] = xl        ? xc[-1]    : 0.f;
        v[5] = xh        ? xc[1]     : 0.f;
        v[6] = (yh&&xl) ? xc[HH-1]  : 0.f;
        v[7] = yh        ? xc[HH]    : 0.f;
        v[8] = (yh&&xh) ? xc[HH+1]  : 0.f;
#pragma unroll
        for (int co = 0; co < 8; co++) {
            const float* w = &s_wm[(co*32+ci)*9];
#pragma unroll
            for (int t = 0; t < 9; t++) am[co] += w[t]*v[t];
        }
        float vc = v[4];
#pragma unroll
        for (int co = 0; co < 32; co++) aa[co] += s_wa[co*32+ci]*vc;
    }
    float nrm2 = 0.f;
#pragma unroll
    for (int c = 0; c < 8; c++) nrm2 += am[c]*am[c];
    float nrm = sqrtf(nrm2);
    float inv = 1.f / fmaxf(nrm, 5e-5f);
    g_nrm[pix] = nrm;
#pragma unroll
    for (int c = 0; c < 8;  c++) {
        g_xe[pix*8+c]  = am[c];
        g_xnu[pix*8+c] = am[c]*inv;
    }
#pragma unroll
    for (int c = 0; c < 32; c++) g_ye[pix*32+c] = aa[c];

    const float4* r4 = (const float4*)s_rot;
    float4 e0 = make_float4(am[0],am[1],am[2],am[3]);
    float4 e1 = make_float4(am[4],am[5],am[6],am[7]);
    for (int h = 0; h < NHASH; h++) {
        float bP = -1e30f, bN = -1e30f; int iP = 0, iN = 0;
        for (int i = 0; i < 64; i++) {
            float4 a = r4[(h*64+i)*2];
            float4 b = r4[(h*64+i)*2+1];
            float r = e0.x*a.x + e0.y*a.y + e0.z*a.z + e0.w*a.w
                    + e1.x*b.x + e1.y*b.y + e1.z*b.z + e1.w*b.w;
            if ( r > bP) { bP =  r; iP = i; }
            if (-r > bN) { bN = -r; iN = i; }
        }
        int code = ((bN > bP) ? (64 + iN) : iP) + h*128;
        g_code[h*L + pix] = code;
        atomicAdd(&s_h[code], 1);
    }
    __syncthreads();
    for (int t = tid; t < NCODES; t += 128) {
        int v = s_h[t];
        if (v) {
            int tile = (t >> 7)*36 + (blockIdx.x >> 3);
            atomicAdd(&g_tileHist[t*NTILES + tile], v);
        }
    }
}

// ---------------- scanA: per-code prefix over tiles (+ re-zero hist) ---------
__global__ void k_scanA() {                            // one warp per code
    int c = blockIdx.x*8 + (threadIdx.x >> 5);
    int lane = threadIdx.x & 31;
    int run = 0;
    for (int base = 0; base < NTILES; base += 32) {
        int t = base + lane;
        int v = 0;
        if (t < NTILES) {
            v = g_tileHist[c*NTILES + t];
            g_tileHist[c*NTILES + t] = 0;
        }
        int incl = v;
#pragma unroll
        for (int o = 1; o < 32; o <<= 1) {
            int u = __shfl_up_sync(0xffffffffu, incl, o);
            if (lane >= o) incl += u;
        }
        if (t < NTILES) g_tileOff[c*NTILES + t] = run + incl - v;
        run += __shfl_sync(0xffffffffu, incl, 31);
    }
    if (lane == 0) g_codeTot[c] = run;
}

// ---------------- scatter (with inline 512-bin global scan) ------------------
__global__ void k_scatter() {                          // 8 warps per tile, stable
    __shared__ int wcnt[8*NCODES];
    __shared__ int s_sc[NCODES];
    int tile = blockIdx.x;
    int tid = threadIdx.x, w = tid >> 5, lane = tid & 31;
    s_sc[tid]       = g_codeTot[tid];
    s_sc[tid + 256] = g_codeTot[tid + 256];
    for (int c = tid; c < 8*NCODES; c += 256) wcnt[c] = 0;
    __syncthreads();
    for (int off = 1; off < NCODES; off <<= 1) {
        int a = (tid        >= off) ? s_sc[tid - off]       : 0;
        int b = (tid + 256  >= off) ? s_sc[tid + 256 - off] : 0;
        __syncthreads();
        s_sc[tid]       += a;
        s_sc[tid + 256] += b;
        __syncthreads();
    }
    int codes[4];
#pragma unroll
    for (int r = 0; r < 4; r++) {
        int p = tile*TILE + w*128 + r*32 + lane;
        int c = codes[r] = g_code[p];
        unsigned mask = __match_any_sync(0xffffffffu, c);
        int leader = __ffs(mask) - 1;
        if (lane == leader) wcnt[w*NCODES + c] += __popc(mask);
        __syncwarp();
    }
    __syncthreads();
    for (int c = tid; c < NCODES; c += 256) {
        int run = ((c == 0) ? 0 : s_sc[c-1]) + g_tileOff[c*NTILES + tile];
#pragma unroll
        for (int ww = 0; ww < 8; ww++) {
            int v = wcnt[ww*NCODES + c];
            wcnt[ww*NCODES + c] = run;
            run += v;
        }
    }
    __syncthreads();
#pragma unroll
    for (int r = 0; r < 4; r++) {
        int p = tile*TILE + w*128 + r*32 + lane;
        int c = codes[r];
        unsigned mask = __match_any_sync(0xffffffffu, c);
        int leader = __ffs(mask) - 1;
        int below  = __popc(mask & ((1u << lane) - 1u));
        int base = 0;
        if (lane == leader) {
            base = wcnt[w*NCODES + c];
            wcnt[w*NCODES + c] = base + __popc(mask);
        }
        base = __shfl_sync(0xffffffffu, base, leader);
        int dest = base + below;
        g_sortIdx[dest] = p;
        g_undo[p] = dest;
        __syncwarp();
    }
}

// ---------------- attention: scalar QK + tensor-core PV (split-tf32) ---------
// Keys unit-norm => score s = q.k <= ||q||; m = ||q|| is a valid softmax max.
// 288 threads = 9 warps. Phase A: thread (q, half) computes probs for half of
// the 48-key tile (scalar FFMA2 chains, log2 domain, bias-folded) -> s_p.
// Phase B: warp w owns queries 16w..16w+15; PV via mma.m16n8k4 tf32 with
// 3-term split emulation (hi*hi + hi*lo + lo*hi), error ~1e-6.
__global__ __launch_bounds__(288, 3) void k_attn() {
    __shared__ int s_l[432];                          // 1728 B
    __shared__ __align__(16) ull   s_kp[216*8];       // packed key pairs (13824 B)
    __shared__ __align__(16) float s_p[KTILE*SPS];    // prob tile [key][query] (29184 B)
    __shared__ __align__(16) float s_y[2][KTILE*SYS]; // value tiles, padded (15360 B)
    __shared__ float s_lsA[2*CHUNK_];
    __shared__ float s_inv[CHUNK_];
    int blk = blockIdx.x;
    int h = blk >> 8, k = blk & 255;
    int tid = threadIdx.x;
    int hb = h*L;
    int kb1 = (k + 255) & 255, kb2 = (k + 1) & 255;
    int baseQ = hb + k*CHUNK_;
    int sb0 = baseQ, sb1 = hb + kb1*CHUNK_, sb2 = hb + kb2*CHUNK_;

    for (int e = tid; e < 432; e += 288) {
        int seg = e / CHUNK_; int r = e - seg*CHUNK_;
        int sb = (seg == 0) ? sb0 : ((seg == 1) ? sb1 : sb2);
        s_l[e] = g_sortIdx[sb + r] % L;
    }
    __syncthreads();

    unsigned int ybase = (unsigned int)__cvta_generic_to_shared(&s_y[0][0]);
    auto stage = [&](int t) {                         // value tile t -> buffer t&1
        unsigned int vd = ybase + (unsigned int)(t & 1) * (KTILE*SYS*4u);
        int base = t*KTILE;
        for (int e = tid; e < KTILE*8; e += 288) {
            int jr = e >> 3, ch = e & 7;
            cp16(vd + jr*(SYS*4u) + ch*16u, g_ye + (size_t)s_l[base + jr]*32 + ch*4);
        }
        asm volatile("cp.async.commit_group;" ::: "memory");
    };
    stage(0);

    // pack key pairs: s_kp[jp*8+d] = (k[2jp][d], k[2jp+1][d])
    for (int e = tid; e < 1728; e += 288) {
        int jp = e >> 3, d = e & 7;
        s_kp[e] = pack2(g_xnu[(size_t)s_l[2*jp]*8 + d], g_xnu[(size_t)s_l[2*jp+1]*8 + d]);
    }

    int q    = (tid < CHUNK_) ? tid : tid - CHUNK_;
    int half = (tid >= CHUNK_) ? 1 : 0;
    ull qq[8];
    ull bias2;
    float m, lsum = 0.f;
    {
        int lq = s_l[q];
        m = g_nrm[lq];
        float m2 = m * LOG2E;
        bias2 = pack2(-m2, -m2);
        const float* qp = g_xe + (size_t)lq*8;
#pragma unroll
        for (int d = 0; d < 8; d++) {
            float qv = qp[d] * LOG2E;
            qq[d] = pack2(qv, qv);
        }
    }
    int lane = tid & 31, w = tid >> 5;
    int m0 = w * 16;                                  // warp's query tile base
    int lr = lane >> 2, lc = lane & 3;
    float dacc[16];
#pragma unroll
    for (int i = 0; i < 16; i++) dacc[i] = 0.f;
    __syncthreads();                                  // s_kp ready

    for (int t = 0; t < NKT; t++) {
        if (t + 1 < NKT) stage(t + 1);
        // ---- phase A: this thread's 12 key pairs of the 48-key tile ---------
        {
            int jp0 = half * 12;
#pragma unroll 3
            for (int jl = 0; jl < 12; jl++) {
                const ulonglong2* kp = (const ulonglong2*)&s_kp[(t*24 + jp0 + jl)*8];
                ulonglong2 k01 = kp[0], k23 = kp[1];
                ulonglong2 k45 = kp[2], k67 = kp[3];
                ull sa = ffma2(qq[0], k01.x, bias2);
                ull sb = ffma2(qq[1], k01.y, 0ull);
                sa = ffma2(qq[2], k23.x, sa);
                sb = ffma2(qq[3], k23.y, sb);
                sa = ffma2(qq[4], k45.x, sa);
                sb = ffma2(qq[5], k45.y, sb);
                sa = ffma2(qq[6], k67.x, sa);
                sb = ffma2(qq[7], k67.y, sb);
                ull sp = fadd2(sa, sb);
                float lo, hi; unpack2(sp, lo, hi);
                float p0 = ex2f(lo);
                float p1 = ex2f(hi);
                lsum += p0 + p1;
                int j0 = 2*(jp0 + jl);
                s_p[j0*SPS + q]     = p0;
                s_p[(j0+1)*SPS + q] = p1;
            }
        }
        if (t + 1 < NKT) { asm volatile("cp.async.wait_group 1;" ::: "memory"); }
        else             { asm volatile("cp.async.wait_group 0;" ::: "memory"); }
        __syncthreads();                              // s_p + value tile t ready
        // ---- phase B: tensor-core P x V (12 k4-steps, 4 N-tiles) ------------
        const float* yb = s_y[t & 1];
#pragma unroll
        for (int s = 0; s < 12; s++) {
            int k0 = s*4;
            const float* pb = &s_p[(size_t)(k0 + lc)*SPS + m0 + lr];
            float a0 = pb[0];
            float a1 = pb[8];
            unsigned a0h = __float_as_uint(a0) & 0xFFFFE000u;
            unsigned a1h = __float_as_uint(a1) & 0xFFFFE000u;
            unsigned a0l = __float_as_uint(a0 - __uint_as_float(a0h));
            unsigned a1l = __float_as_uint(a1 - __uint_as_float(a1h));
            const float* vrow = &yb[(size_t)(k0 + lc)*SYS + lr];
#pragma unroll
            for (int n = 0; n < 4; n++) {
                float b0 = vrow[n*8];
                unsigned b0h = __float_as_uint(b0) & 0xFFFFE000u;
                unsigned b0l = __float_as_uint(b0 - __uint_as_float(b0h));
                float* dd = &dacc[n*4];
                MMA4(dd, a0h, a1h, b0h);
                MMA4(dd, a0h, a1h, b0l);
                MMA4(dd, a0l, a1l, b0h);
            }
        }
        __syncthreads();                              // protect s_p + buffers
    }

    // epilogue: combine lsum halves, write bucket scores + outputs
    s_lsA[half*CHUNK_ + q] = lsum;
    __syncthreads();
    if (tid < CHUNK_) {
        float tot = s_lsA[tid] + s_lsA[CHUNK_ + tid];
        s_inv[tid] = 1.f / tot;
        g_bs[baseQ + tid] = m + __logf(tot);
    }
    __syncthreads();
    float inv0 = s_inv[m0 + lr];
    float inv1 = s_inv[m0 + lr + 8];
#pragma unroll
    for (int n = 0; n < 4; n++) {
        float2 v01 = make_float2(dacc[n*4+0]*inv0, dacc[n*4+1]*inv0);
        float2 v23 = make_float2(dacc[n*4+2]*inv1, dacc[n*4+3]*inv1);
        *(float2*)&g_ret[(size_t)(baseQ + m0 + lr)*32 + n*8 + 2*lc]     = v01;
        *(float2*)&g_ret[(size_t)(baseQ + m0 + lr + 8)*32 + n*8 + 2*lc] = v23;
    }
}

// ---------------- un-sort + cross-hash softmax + residual --------------------
__global__ void k_combine(const float* __restrict__ x, float* __restrict__ out) {
    __shared__ int   s_d[4][32];
    __shared__ float s_p[4][32];
    int tx = threadIdx.x, c = threadIdx.y;
    int l = blockIdx.x*32 + tx;
    if (c < 4) {
        int d = g_undo[c*L + l];
        s_d[c][tx] = d;
        s_p[c][tx] = g_bs[d];
    }
    __syncthreads();
    if (c == 0) {
        float b0 = s_p[0][tx], b1 = s_p[1][tx], b2 = s_p[2][tx], b3 = s_p[3][tx];
        float mm = fmaxf(fmaxf(b0,b1), fmaxf(b2,b3));
        float e0 = __expf(b0-mm), e1 = __expf(b1-mm), e2 = __expf(b2-mm), e3 = __expf(b3-mm);
        float inv = 1.f/(e0+e1+e2+e3);
        s_p[0][tx] = e0*inv; s_p[1][tx] = e1*inv; s_p[2][tx] = e2*inv; s_p[3][tx] = e3*inv;
    }
    __syncthreads();
    float sum = 0.f;
#pragma unroll
    for (int h = 0; h < 4; h++)
        sum += s_p[h][tx] * g_ret[(size_t)s_d[h][tx]*32 + c];
    out[c*L + l] = sum + x[c*L + l];
}

// ---------------- launcher ---------------------------------------------------
extern "C" void kernel_launch(void* const* d_in, const int* in_sizes, int n_in,
                              void* d_out, int out_size) {
    const float* x   = (const float*)d_in[0];
    const float* wm  = (const float*)d_in[1];
    const float* bm  = (const float*)d_in[2];
    const float* wa  = (const float*)d_in[3];
    const float* ba  = (const float*)d_in[4];
    const float* rot = (const float*)d_in[5];
    float* out = (float*)d_out;

    k_embed<<<L/128, 128>>>(x, wm, bm, wa, ba, rot);
    k_scanA<<<64, 256>>>();
    k_scatter<<<NTILES, 256>>>();
    k_attn<<<NHASH*NCHUNK, 288>>>();                 // 4th launch -> profiled
    k_combine<<<L/32, dim3(32,32)>>>(x, out);
}

// round 16
// speedup vs baseline: 1.2758x; 1.2089x over previous
#include <cuda_runtime.h>

#define L 36864
#define HH 192
#define NHASH 4
#define TOT (NHASH*L)        // 147456
#define CHUNK_ 144
#define NCHUNK 256
#define NCODES 512
#define TILE 1024
#define NTILES 144           // TOT / TILE
#define KTILE 48
#define NKT 9                // 432 / KTILE
#define SPS 152              // s_p row stride (floats), bank-conflict-free
#define SYS 40               // s_y row stride (floats), bank-conflict-free
#define LOG2E 1.4426950408889634f

typedef unsigned long long ull;

// ---------------- scratch ----------------------------------------------------
__device__ __align__(16) float g_xe[L*8];        // raw query embed
__device__ __align__(16) float g_xnu[L*8];       // normalized embed (keys)
__device__ float g_nrm[L];                       // ||embed|| per pixel
__device__ __align__(16) float g_ye[L*32];       // value embed
__device__ int   g_code[TOT];
__device__ int   g_tileHist[NCODES*NTILES];      // [code][tile], atomic, re-zeroed by scanA
__device__ int   g_tileOff[NCODES*NTILES];
__device__ int   g_codeTot[NCODES];
__device__ int   g_sortIdx[TOT];
__device__ int   g_undo[TOT];
__device__ __align__(16) float g_ret[TOT*32];
__device__ float g_bs[TOT];

// ---------------- f32x2 / cp.async / mma helpers -----------------------------
__device__ __forceinline__ ull ffma2(ull a, ull b, ull c) {
    ull d;
    asm("fma.rn.f32x2 %0, %1, %2, %3;" : "=l"(d) : "l"(a), "l"(b), "l"(c));
    return d;
}
__device__ __forceinline__ ull fadd2(ull a, ull b) {
    ull d;
    asm("add.rn.f32x2 %0, %1, %2;" : "=l"(d) : "l"(a), "l"(b));
    return d;
}
__device__ __forceinline__ ull pack2(float lo, float hi) {
    ull d;
    asm("mov.b64 %0, {%1, %2};" : "=l"(d)
        : "r"(__float_as_uint(lo)), "r"(__float_as_uint(hi)));
    return d;
}
__device__ __forceinline__ void unpack2(ull v, float& lo, float& hi) {
    unsigned int a, b;
    asm("mov.b64 {%0, %1}, %2;" : "=r"(a), "=r"(b) : "l"(v));
    lo = __uint_as_float(a); hi = __uint_as_float(b);
}
__device__ __forceinline__ float ex2f(float x) {
    float r;
    asm("ex2.approx.f32 %0, %1;" : "=f"(r) : "f"(x));
    return r;
}
__device__ __forceinline__ void cp16(unsigned int dst, const void* src) {
    asm volatile("cp.async.ca.shared.global [%0], [%1], 16;" :: "r"(dst), "l"(src));
}
// m16n8k8 tf32 mma: D += A(16x8) * B(8x8).
// A = {a0:(g,tg), a1:(g+8,tg), a2:(g,tg+4), a3:(g+8,tg+4)}
// B = {b0:(tg,g), b1:(tg+4,g)}   (two stacked k4 halves)
#define MMA8(D, A0, A1, A2, A3, B0, B1) \
    asm volatile("mma.sync.aligned.m16n8k8.row.col.f32.tf32.tf32.f32 " \
        "{%0,%1,%2,%3}, {%4,%5,%6,%7}, {%8,%9}, {%0,%1,%2,%3};" \
        : "+f"((D)[0]), "+f"((D)[1]), "+f"((D)[2]), "+f"((D)[3]) \
        : "r"(A0), "r"(A1), "r"(A2), "r"(A3), "r"(B0), "r"(B1))

// ---------------- K1: convs + hashing + norms + histogram --------------------
__global__ void k_embed(const float* __restrict__ x,
                        const float* __restrict__ wm,
                        const float* __restrict__ bm,
                        const float* __restrict__ wa,
                        const float* __restrict__ ba,
                        const float* __restrict__ rot) {
    __shared__ float s_wm[2304];
    __shared__ float s_wa[1024];
    __shared__ __align__(16) float s_rot[2048];  // transposed: [(h*64+i)][f=8]
    __shared__ float s_bm[8];
    __shared__ float s_ba[32];
    __shared__ int   s_h[NCODES];
    int tid = threadIdx.x;
    for (int t = tid; t < 2304; t += 128) s_wm[t] = wm[t];
    for (int t = tid; t < 1024; t += 128) s_wa[t] = wa[t];
    for (int t = tid; t < 2048; t += 128) {
        int f = t >> 8; int rem = t & 255;
        s_rot[rem*8 + f] = rot[t];
    }
    for (int t = tid; t < NCODES; t += 128) s_h[t] = 0;
    if (tid < 8)  s_bm[tid] = bm[tid];
    if (tid < 32) s_ba[tid] = ba[tid];
    __syncthreads();

    int pix = blockIdx.x*128 + tid;
    int py = pix / HH, px = pix - py*HH;
    float am[8], aa[32];
#pragma unroll
    for (int c = 0; c < 8;  c++) am[c] = s_bm[c];
#pragma unroll
    for (int c = 0; c < 32; c++) aa[c] = s_ba[c];

    bool yl = py > 0, yh = py < HH-1, xl = px > 0, xh = px < HH-1;
    for (int ci = 0; ci < 32; ci++) {
        const float* xc = x + ci*L + py*HH + px;
        float v[9];
        v[4] = xc[0];
        v[0] = (yl&&xl) ? xc[-HH-1] : 0.f;
        v[1] = yl        ? xc[-HH]   : 0.f;
        v[2] = (yl&&xh) ? xc[-HH+1] : 0.f;
        v[3] = xl        ? xc[-1]    : 0.f;
        v[5] = xh        ? xc[1]     : 0.f;
        v[6] = (yh&&xl) ? xc[HH-1]  : 0.f;
        v[7] = yh        ? xc[HH]    : 0.f;
        v[8] = (yh&&xh) ? xc[HH+1]  : 0.f;
#pragma unroll
        for (int co = 0; co < 8; co++) {
            const float* w = &s_wm[(co*32+ci)*9];
#pragma unroll
            for (int t = 0; t < 9; t++) am[co] += w[t]*v[t];
        }
        float vc = v[4];
#pragma unroll
        for (int co = 0; co < 32; co++) aa[co] += s_wa[co*32+ci]*vc;
    }
    float nrm2 = 0.f;
#pragma unroll
    for (int c = 0; c < 8; c++) nrm2 += am[c]*am[c];
    float nrm = sqrtf(nrm2);
    float inv = 1.f / fmaxf(nrm, 5e-5f);
    g_nrm[pix] = nrm;
#pragma unroll
    for (int c = 0; c < 8;  c++) {
        g_xe[pix*8+c]  = am[c];
        g_xnu[pix*8+c] = am[c]*inv;
    }
#pragma unroll
    for (int c = 0; c < 32; c++) g_ye[pix*32+c] = aa[c];

    const float4* r4 = (const float4*)s_rot;
    float4 e0 = make_float4(am[0],am[1],am[2],am[3]);
    float4 e1 = make_float4(am[4],am[5],am[6],am[7]);
    for (int h = 0; h < NHASH; h++) {
        float bP = -1e30f, bN = -1e30f; int iP = 0, iN = 0;
        for (int i = 0; i < 64; i++) {
            float4 a = r4[(h*64+i)*2];
            float4 b = r4[(h*64+i)*2+1];
            float r = e0.x*a.x + e0.y*a.y + e0.z*a.z + e0.w*a.w
                    + e1.x*b.x + e1.y*b.y + e1.z*b.z + e1.w*b.w;
            if ( r > bP) { bP =  r; iP = i; }
            if (-r > bN) { bN = -r; iN = i; }
        }
        int code = ((bN > bP) ? (64 + iN) : iP) + h*128;
        g_code[h*L + pix] = code;
        atomicAdd(&s_h[code], 1);
    }
    __syncthreads();
    for (int t = tid; t < NCODES; t += 128) {
        int v = s_h[t];
        if (v) {
            int tile = (t >> 7)*36 + (blockIdx.x >> 3);
            atomicAdd(&g_tileHist[t*NTILES + tile], v);
        }
    }
}

// ---------------- scanA: per-code prefix over tiles (+ re-zero hist) ---------
__global__ void k_scanA() {                            // one warp per code
    int c = blockIdx.x*8 + (threadIdx.x >> 5);
    int lane = threadIdx.x & 31;
    int run = 0;
    for (int base = 0; base < NTILES; base += 32) {
        int t = base + lane;
        int v = 0;
        if (t < NTILES) {
            v = g_tileHist[c*NTILES + t];
            g_tileHist[c*NTILES + t] = 0;
        }
        int incl = v;
#pragma unroll
        for (int o = 1; o < 32; o <<= 1) {
            int u = __shfl_up_sync(0xffffffffu, incl, o);
            if (lane >= o) incl += u;
        }
        if (t < NTILES) g_tileOff[c*NTILES + t] = run + incl - v;
        run += __shfl_sync(0xffffffffu, incl, 31);
    }
    if (lane == 0) g_codeTot[c] = run;
}

// ---------------- scatter (with inline 512-bin global scan) ------------------
__global__ void k_scatter() {                          // 8 warps per tile, stable
    __shared__ int wcnt[8*NCODES];
    __shared__ int s_sc[NCODES];
    int tile = blockIdx.x;
    int tid = threadIdx.x, w = tid >> 5, lane = tid & 31;
    s_sc[tid]       = g_codeTot[tid];
    s_sc[tid + 256] = g_codeTot[tid + 256];
    for (int c = tid; c < 8*NCODES; c += 256) wcnt[c] = 0;
    __syncthreads();
    for (int off = 1; off < NCODES; off <<= 1) {
        int a = (tid        >= off) ? s_sc[tid - off]       : 0;
        int b = (tid + 256  >= off) ? s_sc[tid + 256 - off] : 0;
        __syncthreads();
        s_sc[tid]       += a;
        s_sc[tid + 256] += b;
        __syncthreads();
    }
    int codes[4];
#pragma unroll
    for (int r = 0; r < 4; r++) {
        int p = tile*TILE + w*128 + r*32 + lane;
        int c = codes[r] = g_code[p];
        unsigned mask = __match_any_sync(0xffffffffu, c);
        int leader = __ffs(mask) - 1;
        if (lane == leader) wcnt[w*NCODES + c] += __popc(mask);
        __syncwarp();
    }
    __syncthreads();
    for (int c = tid; c < NCODES; c += 256) {
        int run = ((c == 0) ? 0 : s_sc[c-1]) + g_tileOff[c*NTILES + tile];
#pragma unroll
        for (int ww = 0; ww < 8; ww++) {
            int v = wcnt[ww*NCODES + c];
            wcnt[ww*NCODES + c] = run;
            run += v;
        }
    }
    __syncthreads();
#pragma unroll
    for (int r = 0; r < 4; r++) {
        int p = tile*TILE + w*128 + r*32 + lane;
        int c = codes[r];
        unsigned mask = __match_any_sync(0xffffffffu, c);
        int leader = __ffs(mask) - 1;
        int below  = __popc(mask & ((1u << lane) - 1u));
        int base = 0;
        if (lane == leader) {
            base = wcnt[w*NCODES + c];
            wcnt[w*NCODES + c] = base + __popc(mask);
        }
        base = __shfl_sync(0xffffffffu, base, leader);
        int dest = base + below;
        g_sortIdx[dest] = p;
        g_undo[p] = dest;
        __syncwarp();
    }
}

// ---------------- attention: scalar QK + tensor-core PV (k8, split-tf32) -----
// Keys unit-norm => score s = q.k <= ||q||; m = ||q|| is a valid softmax max.
// 288 threads = 9 warps. Phase A: thread (q, half) computes probs for half of
// the 48-key tile (scalar FFMA2 chains, log2 domain, bias-folded) -> s_p.
// Phase B: warp w owns queries 16w..16w+15; PV via mma.m16n8k8 tf32 with
// 3-term split emulation (hi*hi + hi*lo + lo*hi), error ~1e-6.
__global__ __launch_bounds__(288, 3) void k_attn() {
    __shared__ int s_l[432];                          // 1728 B
    __shared__ __align__(16) ull   s_kp[216*8];       // packed key pairs (13824 B)
    __shared__ __align__(16) float s_p[KTILE*SPS];    // prob tile [key][query] (29184 B)
    __shared__ __align__(16) float s_y[2][KTILE*SYS]; // value tiles, padded (15360 B)
    __shared__ float s_lsA[2*CHUNK_];
    __shared__ float s_inv[CHUNK_];
    int blk = blockIdx.x;
    int h = blk >> 8, k = blk & 255;
    int tid = threadIdx.x;
    int hb = h*L;
    int kb1 = (k + 255) & 255, kb2 = (k + 1) & 255;
    int baseQ = hb + k*CHUNK_;
    int sb0 = baseQ, sb1 = hb + kb1*CHUNK_, sb2 = hb + kb2*CHUNK_;

    for (int e = tid; e < 432; e += 288) {
        int seg = e / CHUNK_; int r = e - seg*CHUNK_;
        int sb = (seg == 0) ? sb0 : ((seg == 1) ? sb1 : sb2);
        s_l[e] = g_sortIdx[sb + r] % L;
    }
    __syncthreads();

    unsigned int ybase = (unsigned int)__cvta_generic_to_shared(&s_y[0][0]);
    auto stage = [&](int t) {                         // value tile t -> buffer t&1
        unsigned int vd = ybase + (unsigned int)(t & 1) * (KTILE*SYS*4u);
        int base = t*KTILE;
        for (int e = tid; e < KTILE*8; e += 288) {
            int jr = e >> 3, ch = e & 7;
            cp16(vd + jr*(SYS*4u) + ch*16u, g_ye + (size_t)s_l[base + jr]*32 + ch*4);
        }
        asm volatile("cp.async.commit_group;" ::: "memory");
    };
    stage(0);

    // pack key pairs: s_kp[jp*8+d] = (k[2jp][d], k[2jp+1][d])
    for (int e = tid; e < 1728; e += 288) {
        int jp = e >> 3, d = e & 7;
        s_kp[e] = pack2(g_xnu[(size_t)s_l[2*jp]*8 + d], g_xnu[(size_t)s_l[2*jp+1]*8 + d]);
    }

    int q    = (tid < CHUNK_) ? tid : tid - CHUNK_;
    int half = (tid >= CHUNK_) ? 1 : 0;
    ull qq[8];
    ull bias2;
    float m, lsum = 0.f;
    {
        int lq = s_l[q];
        m = g_nrm[lq];
        float m2 = m * LOG2E;
        bias2 = pack2(-m2, -m2);
        const float* qp = g_xe + (size_t)lq*8;
#pragma unroll
        for (int d = 0; d < 8; d++) {
            float qv = qp[d] * LOG2E;
            qq[d] = pack2(qv, qv);
        }
    }
    int lane = tid & 31, w = tid >> 5;
    int m0 = w * 16;                                  // warp's query tile base
    int lr = lane >> 2, lc = lane & 3;
    float dacc[16];
#pragma unroll
    for (int i = 0; i < 16; i++) dacc[i] = 0.f;
    __syncthreads();                                  // s_kp ready

    for (int t = 0; t < NKT; t++) {
        if (t + 1 < NKT) stage(t + 1);
        // ---- phase A: this thread's 12 key pairs of the 48-key tile ---------
        {
            int jp0 = half * 12;
#pragma unroll 3
            for (int jl = 0; jl < 12; jl++) {
                const ulonglong2* kp = (const ulonglong2*)&s_kp[(t*24 + jp0 + jl)*8];
                ulonglong2 k01 = kp[0], k23 = kp[1];
                ulonglong2 k45 = kp[2], k67 = kp[3];
                ull sa = ffma2(qq[0], k01.x, bias2);
                ull sb = ffma2(qq[1], k01.y, 0ull);
                sa = ffma2(qq[2], k23.x, sa);
                sb = ffma2(qq[3], k23.y, sb);
                sa = ffma2(qq[4], k45.x, sa);
                sb = ffma2(qq[5], k45.y, sb);
                sa = ffma2(qq[6], k67.x, sa);
                sb = ffma2(qq[7], k67.y, sb);
                ull sp = fadd2(sa, sb);
                float lo, hi; unpack2(sp, lo, hi);
                float p0 = ex2f(lo);
                float p1 = ex2f(hi);
                lsum += p0 + p1;
                int j0 = 2*(jp0 + jl);
                s_p[j0*SPS + q]     = p0;
                s_p[(j0+1)*SPS + q] = p1;
            }
        }
        if (t + 1 < NKT) { asm volatile("cp.async.wait_group 1;" ::: "memory"); }
        else             { asm volatile("cp.async.wait_group 0;" ::: "memory"); }
        __syncthreads();                              // s_p + value tile t ready
        // ---- phase B: tensor-core P x V (6 k8-steps, 4 N-tiles) -------------
        const float* yb = s_y[t & 1];
#pragma unroll
        for (int s = 0; s < 6; s++) {
            int k0 = s*8;
            const float* pb  = &s_p[(size_t)(k0 + lc)*SPS + m0 + lr];
            const float* pb2 = pb + 4*SPS;
            float a0 = pb[0],  a1 = pb[8];
            float a2 = pb2[0], a3 = pb2[8];
            unsigned a0h = __float_as_uint(a0) & 0xFFFFE000u;
            unsigned a1h = __float_as_uint(a1) & 0xFFFFE000u;
            unsigned a2h = __float_as_uint(a2) & 0xFFFFE000u;
            unsigned a3h = __float_as_uint(a3) & 0xFFFFE000u;
            unsigned a0l = __float_as_uint(a0 - __uint_as_float(a0h));
            unsigned a1l = __float_as_uint(a1 - __uint_as_float(a1h));
            unsigned a2l = __float_as_uint(a2 - __uint_as_float(a2h));
            unsigned a3l = __float_as_uint(a3 - __uint_as_float(a3h));
            const float* vrow0 = &yb[(size_t)(k0 + lc)*SYS + lr];
            const float* vrow1 = vrow0 + 4*SYS;
#pragma unroll
            for (int n = 0; n < 4; n++) {
                float b0 = vrow0[n*8];
                float b1 = vrow1[n*8];
                unsigned b0h = __float_as_uint(b0) & 0xFFFFE000u;
                unsigned b1h = __float_as_uint(b1) & 0xFFFFE000u;
                unsigned b0l = __float_as_uint(b0 - __uint_as_float(b0h));
                unsigned b1l = __float_as_uint(b1 - __uint_as_float(b1h));
                float* dd = &dacc[n*4];
                MMA8(dd, a0h, a1h, a2h, a3h, b0h, b1h);
                MMA8(dd, a0h, a1h, a2h, a3h, b0l, b1l);
                MMA8(dd, a0l, a1l, a2l, a3l, b0h, b1h);
            }
        }
        __syncthreads();                              // protect s_p + buffers
    }

    // epilogue: combine lsum halves, write bucket scores + outputs
    s_lsA[half*CHUNK_ + q] = lsum;
    __syncthreads();
    if (tid < CHUNK_) {
        float tot = s_lsA[tid] + s_lsA[CHUNK_ + tid];
        s_inv[tid] = 1.f / tot;
        g_bs[baseQ + tid] = m + __logf(tot);
    }
    __syncthreads();
    float inv0 = s_inv[m0 + lr];
    float inv1 = s_inv[m0 + lr + 8];
#pragma unroll
    for (int n = 0; n < 4; n++) {
        float2 v01 = make_float2(dacc[n*4+0]*inv0, dacc[n*4+1]*inv0);
        float2 v23 = make_float2(dacc[n*4+2]*inv1, dacc[n*4+3]*inv1);
        *(float2*)&g_ret[(size_t)(baseQ + m0 + lr)*32 + n*8 + 2*lc]     = v01;
        *(float2*)&g_ret[(size_t)(baseQ + m0 + lr + 8)*32 + n*8 + 2*lc] = v23;
    }
}

// ---------------- un-sort + cross-hash softmax + residual --------------------
__global__ void k_combine(const float* __restrict__ x, float* __restrict__ out) {
    __shared__ int   s_d[4][32];
    __shared__ float s_p[4][32];
    int tx = threadIdx.x, c = threadIdx.y;
    int l = blockIdx.x*32 + tx;
    if (c < 4) {
        int d = g_undo[c*L + l];
        s_d[c][tx] = d;
        s_p[c][tx] = g_bs[d];
    }
    __syncthreads();
    if (c == 0) {
        float b0 = s_p[0][tx], b1 = s_p[1][tx], b2 = s_p[2][tx], b3 = s_p[3][tx];
        float mm = fmaxf(fmaxf(b0,b1), fmaxf(b2,b3));
        float e0 = __expf(b0-mm), e1 = __expf(b1-mm), e2 = __expf(b2-mm), e3 = __expf(b3-mm);
        float inv = 1.f/(e0+e1+e2+e3);
        s_p[0][tx] = e0*inv; s_p[1][tx] = e1*inv; s_p[2][tx] = e2*inv; s_p[3][tx] = e3*inv;
    }
    __syncthreads();
    float sum = 0.f;
#pragma unroll
    for (int h = 0; h < 4; h++)
        sum += s_p[h][tx] * g_ret[(size_t)s_d[h][tx]*32 + c];
    out[c*L + l] = sum + x[c*L + l];
}

// ---------------- launcher ---------------------------------------------------
extern "C" void kernel_launch(void* const* d_in, const int* in_sizes, int n_in,
                              void* d_out, int out_size) {
    const float* x   = (const float*)d_in[0];
    const float* wm  = (const float*)d_in[1];
    const float* bm  = (const float*)d_in[2];
    const float* wa  = (const float*)d_in[3];
    const float* ba  = (const float*)d_in[4];
    const float* rot = (const float*)d_in[5];
    float* out = (float*)d_out;

    k_embed<<<L/128, 128>>>(x, wm, bm, wa, ba, rot);
    k_scanA<<<64, 256>>>();
    k_scatter<<<NTILES, 256>>>();
    k_attn<<<NHASH*NCHUNK, 288>>>();                 // 4th launch -> profiled
    k_combine<<<L/32, dim3(32,32)>>>(x, out);
}

// round 17
// speedup vs baseline: 1.3520x; 1.0597x over previous
#include <cuda_runtime.h>

#define L 36864
#define HH 192
#define NHASH 4
#define TOT (NHASH*L)        // 147456
#define CHUNK_ 144
#define NCHUNK 256
#define NCODES 512
#define TILE 1024
#define NTILES 144           // TOT / TILE
#define KTILE 48
#define NKT 9                // 432 / KTILE
#define SKT 440              // s_kT row stride (floats)
#define SYS 40               // s_y row stride (floats), bank-conflict-free
#define LOG2E 1.4426950408889634f

typedef unsigned long long ull;

// ---------------- scratch ----------------------------------------------------
__device__ __align__(16) float g_xe[L*8];        // raw query embed
__device__ __align__(16) float g_xnu[L*8];       // normalized embed (keys)
__device__ float g_nrm[L];                       // ||embed|| per pixel
__device__ __align__(16) float g_ye[L*32];       // value embed
__device__ int   g_code[TOT];
__device__ int   g_tileHist[NCODES*NTILES];      // [code][tile], atomic, re-zeroed by scanA
__device__ int   g_tileOff[NCODES*NTILES];
__device__ int   g_codeTot[NCODES];
__device__ int   g_sortIdx[TOT];
__device__ int   g_undo[TOT];
__device__ __align__(16) float g_ret[TOT*32];
__device__ float g_bs[TOT];

// ---------------- helpers -----------------------------------------------------
__device__ __forceinline__ float ex2f(float x) {
    float r;
    asm("ex2.approx.f32 %0, %1;" : "=f"(r) : "f"(x));
    return r;
}
__device__ __forceinline__ void cp16(unsigned int dst, const void* src) {
    asm volatile("cp.async.ca.shared.global [%0], [%1], 16;" :: "r"(dst), "l"(src));
}
__device__ __forceinline__ unsigned tfhi(float f) {
    return __float_as_uint(f) & 0xFFFFE000u;
}
__device__ __forceinline__ unsigned tflo(float f, unsigned h) {
    return __float_as_uint(f - __uint_as_float(h));
}
// m16n8k8 tf32 mma: D += A(16x8) * B(8x8).
// A = {a0:(g,tg), a1:(g+8,tg), a2:(g,tg+4), a3:(g+8,tg+4)}
// B = {b0:(tg,g), b1:(tg+4,g)};  D = {d0:(g,2tg), d1:(g,2tg+1), d2/d3: rows +8}
#define MMA8(D, A0, A1, A2, A3, B0, B1) \
    asm volatile("mma.sync.aligned.m16n8k8.row.col.f32.tf32.tf32.f32 " \
        "{%0,%1,%2,%3}, {%4,%5,%6,%7}, {%8,%9}, {%0,%1,%2,%3};" \
        : "+f"((D)[0]), "+f"((D)[1]), "+f"((D)[2]), "+f"((D)[3]) \
        : "r"(A0), "r"(A1), "r"(A2), "r"(A3), "r"(B0), "r"(B1))

// ---------------- K1: convs + hashing + norms + histogram --------------------
__global__ void k_embed(const float* __restrict__ x,
                        const float* __restrict__ wm,
                        const float* __restrict__ bm,
                        const float* __restrict__ wa,
                        const float* __restrict__ ba,
                        const float* __restrict__ rot) {
    __shared__ float s_wm[2304];
    __shared__ float s_wa[1024];
    __shared__ __align__(16) float s_rot[2048];  // transposed: [(h*64+i)][f=8]
    __shared__ float s_bm[8];
    __shared__ float s_ba[32];
    __shared__ int   s_h[NCODES];
    int tid = threadIdx.x;
    for (int t = tid; t < 2304; t += 128) s_wm[t] = wm[t];
    for (int t = tid; t < 1024; t += 128) s_wa[t] = wa[t];
    for (int t = tid; t < 2048; t += 128) {
        int f = t >> 8; int rem = t & 255;
        s_rot[rem*8 + f] = rot[t];
    }
    for (int t = tid; t < NCODES; t += 128) s_h[t] = 0;
    if (tid < 8)  s_bm[tid] = bm[tid];
    if (tid < 32) s_ba[tid] = ba[tid];
    __syncthreads();

    int pix = blockIdx.x*128 + tid;
    int py = pix / HH, px = pix - py*HH;
    float am[8], aa[32];
#pragma unroll
    for (int c = 0; c < 8;  c++) am[c] = s_bm[c];
#pragma unroll
    for (int c = 0; c < 32; c++) aa[c] = s_ba[c];

    bool yl = py > 0, yh = py < HH-1, xl = px > 0, xh = px < HH-1;
    for (int ci = 0; ci < 32; ci++) {
        const float* xc = x + ci*L + py*HH + px;
        float v[9];
        v[4] = xc[0];
        v[0] = (yl&&xl) ? xc[-HH-1] : 0.f;
        v[1] = yl        ? xc[-HH]   : 0.f;
        v[2] = (yl&&xh) ? xc[-HH+1] : 0.f;
        v[3] = xl        ? xc[-1]    : 0.f;
        v[5] = xh        ? xc[1]     : 0.f;
        v[6] = (yh&&xl) ? xc[HH-1]  : 0.f;
        v[7] = yh        ? xc[HH]    : 0.f;
        v[8] = (yh&&xh) ? xc[HH+1]  : 0.f;
#pragma unroll
        for (int co = 0; co < 8; co++) {
            const float* w = &s_wm[(co*32+ci)*9];
#pragma unroll
            for (int t = 0; t < 9; t++) am[co] += w[t]*v[t];
        }
        float vc = v[4];
#pragma unroll
        for (int co = 0; co < 32; co++) aa[co] += s_wa[co*32+ci]*vc;
    }
    float nrm2 = 0.f;
#pragma unroll
    for (int c = 0; c < 8; c++) nrm2 += am[c]*am[c];
    float nrm = sqrtf(nrm2);
    float inv = 1.f / fmaxf(nrm, 5e-5f);
    g_nrm[pix] = nrm;
#pragma unroll
    for (int c = 0; c < 8;  c++) {
        g_xe[pix*8+c]  = am[c];
        g_xnu[pix*8+c] = am[c]*inv;
    }
#pragma unroll
    for (int c = 0; c < 32; c++) g_ye[pix*32+c] = aa[c];

    const float4* r4 = (const float4*)s_rot;
    float4 e0 = make_float4(am[0],am[1],am[2],am[3]);
    float4 e1 = make_float4(am[4],am[5],am[6],am[7]);
    for (int h = 0; h < NHASH; h++) {
        float bP = -1e30f, bN = -1e30f; int iP = 0, iN = 0;
        for (int i = 0; i < 64; i++) {
            float4 a = r4[(h*64+i)*2];
            float4 b = r4[(h*64+i)*2+1];
            float r = e0.x*a.x + e0.y*a.y + e0.z*a.z + e0.w*a.w
                    + e1.x*b.x + e1.y*b.y + e1.z*b.z + e1.w*b.w;
            if ( r > bP) { bP =  r; iP = i; }
            if (-r > bN) { bN = -r; iN = i; }
        }
        int code = ((bN > bP) ? (64 + iN) : iP) + h*128;
        g_code[h*L + pix] = code;
        atomicAdd(&s_h[code], 1);
    }
    __syncthreads();
    for (int t = tid; t < NCODES; t += 128) {
        int v = s_h[t];
        if (v) {
            int tile = (t >> 7)*36 + (blockIdx.x >> 3);
            atomicAdd(&g_tileHist[t*NTILES + tile], v);
        }
    }
}

// ---------------- scanA: per-code prefix over tiles (+ re-zero hist) ---------
__global__ void k_scanA() {                            // one warp per code
    int c = blockIdx.x*8 + (threadIdx.x >> 5);
    int lane = threadIdx.x & 31;
    int run = 0;
    for (int base = 0; base < NTILES; base += 32) {
        int t = base + lane;
        int v = 0;
        if (t < NTILES) {
            v = g_tileHist[c*NTILES + t];
            g_tileHist[c*NTILES + t] = 0;
        }
        int incl = v;
#pragma unroll
        for (int o = 1; o < 32; o <<= 1) {
            int u = __shfl_up_sync(0xffffffffu, incl, o);
            if (lane >= o) incl += u;
        }
        if (t < NTILES) g_tileOff[c*NTILES + t] = run + incl - v;
        run += __shfl_sync(0xffffffffu, incl, 31);
    }
    if (lane == 0) g_codeTot[c] = run;
}

// ---------------- scatter (with inline 512-bin global scan) ------------------
__global__ void k_scatter() {                          // 8 warps per tile, stable
    __shared__ int wcnt[8*NCODES];
    __shared__ int s_sc[NCODES];
    int tile = blockIdx.x;
    int tid = threadIdx.x, w = tid >> 5, lane = tid & 31;
    s_sc[tid]       = g_codeTot[tid];
    s_sc[tid + 256] = g_codeTot[tid + 256];
    for (int c = tid; c < 8*NCODES; c += 256) wcnt[c] = 0;
    __syncthreads();
    for (int off = 1; off < NCODES; off <<= 1) {
        int a = (tid        >= off) ? s_sc[tid - off]       : 0;
        int b = (tid + 256  >= off) ? s_sc[tid + 256 - off] : 0;
        __syncthreads();
        s_sc[tid]       += a;
        s_sc[tid + 256] += b;
        __syncthreads();
    }
    int codes[4];
#pragma unroll
    for (int r = 0; r < 4; r++) {
        int p = tile*TILE + w*128 + r*32 + lane;
        int c = codes[r] = g_code[p];
        unsigned mask = __match_any_sync(0xffffffffu, c);
        int leader = __ffs(mask) - 1;
        if (lane == leader) wcnt[w*NCODES + c] += __popc(mask);
        __syncwarp();
    }
    __syncthreads();
    for (int c = tid; c < NCODES; c += 256) {
        int run = ((c == 0) ? 0 : s_sc[c-1]) + g_tileOff[c*NTILES + tile];
#pragma unroll
        for (int ww = 0; ww < 8; ww++) {
            int v = wcnt[ww*NCODES + c];
            wcnt[ww*NCODES + c] = run;
            run += v;
        }
    }
    __syncthreads();
#pragma unroll
    for (int r = 0; r < 4; r++) {
        int p = tile*TILE + w*128 + r*32 + lane;
        int c = codes[r];
        unsigned mask = __match_any_sync(0xffffffffu, c);
        int leader = __ffs(mask) - 1;
        int below  = __popc(mask & ((1u << lane) - 1u));
        int base = 0;
        if (lane == leader) {
            base = wcnt[w*NCODES + c];
            wcnt[w*NCODES + c] = base + __popc(mask);
        }
        base = __shfl_sync(0xffffffffu, base, leader);
        int dest = base + below;
        g_sortIdx[dest] = p;
        g_undo[p] = dest;
        __syncwarp();
    }
}

// ---------------- attention: full tensor-core QK + PV (split-tf32) -----------
// Keys unit-norm => score s = q.k <= ||q||; m = ||q|| is a valid softmax max.
// 288 threads = 9 warps; warp w owns queries m0=16w .. m0+15.
// Per 8-key group s: QK via one m16n8k8 (k = 8 embed dims, 3-term split, bias
// -m*log2e folded into the accumulator init) -> exp in regs -> PV m16n8k8
// (3-term split) consuming P directly from the D fragment. V rows are
// permuted at cp.async staging (slot = invpi(key)) so the D->A key order
// matches without any transpose.
__global__ __launch_bounds__(288, 3) void k_attn() {
    __shared__ int s_l[432];                          // 1728 B
    __shared__ __align__(16) float s_kT[8*SKT];       // keys transposed (14080 B)
    __shared__ __align__(16) float s_y[2][KTILE*SYS]; // value tiles, permuted (15360 B)
    int blk = blockIdx.x;
    int h = blk >> 8, k = blk & 255;
    int tid = threadIdx.x;
    int hb = h*L;
    int kb1 = (k + 255) & 255, kb2 = (k + 1) & 255;
    int baseQ = hb + k*CHUNK_;
    int sb0 = baseQ, sb1 = hb + kb1*CHUNK_, sb2 = hb + kb2*CHUNK_;

    for (int e = tid; e < 432; e += 288) {
        int seg = e / CHUNK_; int r = e - seg*CHUNK_;
        int sb = (seg == 0) ? sb0 : ((seg == 1) ? sb1 : sb2);
        s_l[e] = g_sortIdx[sb + r] % L;
    }
    __syncthreads();

    // stage ALL keys transposed: s_kT[dim][key]
    for (int e = tid; e < 864; e += 288) {
        int key = e >> 1, hf = e & 1;
        float4 f4 = *(const float4*)(g_xnu + (size_t)s_l[key]*8 + hf*4);
        s_kT[(hf*4+0)*SKT + key] = f4.x;
        s_kT[(hf*4+1)*SKT + key] = f4.y;
        s_kT[(hf*4+2)*SKT + key] = f4.z;
        s_kT[(hf*4+3)*SKT + key] = f4.w;
    }

    unsigned int ybase = (unsigned int)__cvta_generic_to_shared(&s_y[0][0]);
    auto stage = [&](int t) {                         // value tile t -> buffer t&1
        unsigned int vd = ybase + (unsigned int)(t & 1) * (KTILE*SYS*4u);
        int base = t*KTILE;
        for (int e = tid; e < KTILE*8; e += 288) {
            int jr = e >> 3, ch = e & 7;
            // slot = group | invpi(jr&7): even key o -> o/2, odd -> 4 + o/2
            int o = jr & 7;
            int slot = (jr & ~7) | ((o >> 1) + ((o & 1) << 2));
            cp16(vd + slot*(SYS*4u) + ch*16u, g_ye + (size_t)s_l[base + jr]*32 + ch*4);
        }
        asm volatile("cp.async.commit_group;" ::: "memory");
    };
    stage(0);

    int lane = tid & 31, w = tid >> 5;
    int m0 = w * 16;
    int g = lane >> 2, tg = lane & 3;
    // Q fragment (loop-invariant): queries m0+g, m0+g+8, dims tg, tg+4
    int l0 = s_l[m0 + g], l1 = s_l[m0 + g + 8];
    float mA = g_nrm[l0], mB = g_nrm[l1];
    float m2A = mA * LOG2E, m2B = mB * LOG2E;
    float q00 = g_xe[(size_t)l0*8 + tg]     * LOG2E;   // a0: (g,   tg)
    float q10 = g_xe[(size_t)l1*8 + tg]     * LOG2E;   // a1: (g+8, tg)
    float q01 = g_xe[(size_t)l0*8 + tg + 4] * LOG2E;   // a2: (g,   tg+4)
    float q11 = g_xe[(size_t)l1*8 + tg + 4] * LOG2E;   // a3: (g+8, tg+4)
    unsigned qh0 = tfhi(q00), qh1 = tfhi(q10), qh2 = tfhi(q01), qh3 = tfhi(q11);
    unsigned ql0 = tflo(q00, qh0), ql1 = tflo(q10, qh1);
    unsigned ql2 = tflo(q01, qh2), ql3 = tflo(q11, qh3);

    float dacc[16];
#pragma unroll
    for (int i = 0; i < 16; i++) dacc[i] = 0.f;
    float lsum0 = 0.f, lsum1 = 0.f;

    for (int t = 0; t < NKT; t++) {
        asm volatile("cp.async.wait_group 0;" ::: "memory");
        __syncthreads();                              // value tile t + (t=0) keys ready
        if (t + 1 < NKT) stage(t + 1);                // buffer (t+1)&1 free past sync
        const float* yb = s_y[t & 1];
        int K0 = t * KTILE;
#pragma unroll
        for (int s = 0; s < 6; s++) {
            // ---- QK: one k8 step over the 8 embed dims, 3-term split --------
            float b0 = s_kT[tg*SKT     + K0 + 8*s + g];
            float b1 = s_kT[(tg+4)*SKT + K0 + 8*s + g];
            unsigned b0h = tfhi(b0), b1h = tfhi(b1);
            unsigned b0l = tflo(b0, b0h), b1l = tflo(b1, b1h);
            float sacc[4];
            sacc[0] = -m2A; sacc[1] = -m2A;           // rows g   (query m0+g)
            sacc[2] = -m2B; sacc[3] = -m2B;           // rows g+8 (query m0+g+8)
            MMA8(sacc, qh0, qh1, qh2, qh3, b0h, b1h);
            MMA8(sacc, qh0, qh1, qh2, qh3, b0l, b1l);
            MMA8(sacc, ql0, ql1, ql2, ql3, b0h, b1h);
            // ---- softmax probs in regs --------------------------------------
            float p0 = ex2f(sacc[0]);                 // (g,   key 2tg)
            float p1 = ex2f(sacc[1]);                 // (g,   key 2tg+1)
            float p2 = ex2f(sacc[2]);                 // (g+8, key 2tg)
            float p3 = ex2f(sacc[3]);                 // (g+8, key 2tg+1)
            lsum0 += p0 + p1;
            lsum1 += p2 + p3;
            // ---- PV A-fragment: a0=(g,pos tg)=key 2tg=p0; a2=(g,pos tg+4)=p1
            unsigned a0h = tfhi(p0), a2h = tfhi(p1), a1h = tfhi(p2), a3h = tfhi(p3);
            unsigned a0l = tflo(p0, a0h), a2l = tflo(p1, a2h);
            unsigned a1l = tflo(p2, a1h), a3l = tflo(p3, a3h);
            const float* vr0 = &yb[(size_t)(8*s + tg)*SYS + g];
            const float* vr1 = vr0 + 4*SYS;
#pragma unroll
            for (int n = 0; n < 4; n++) {
                float vb0 = vr0[n*8], vb1 = vr1[n*8];
                unsigned vb0h = tfhi(vb0), vb1h = tfhi(vb1);
                unsigned vb0l = tflo(vb0, vb0h), vb1l = tflo(vb1, vb1h);
                float* dd = &dacc[n*4];
                MMA8(dd, a0h, a1h, a2h, a3h, vb0h, vb1h);
                MMA8(dd, a0h, a1h, a2h, a3h, vb0l, vb1l);
                MMA8(dd, a0l, a1l, a2l, a3l, vb0h, vb1h);
            }
        }
    }

    // reduce lsum across the 4 lanes sharing each query row (tg bits = lane 0,1)
    lsum0 += __shfl_xor_sync(0xffffffffu, lsum0, 1);
    lsum0 += __shfl_xor_sync(0xffffffffu, lsum0, 2);
    lsum1 += __shfl_xor_sync(0xffffffffu, lsum1, 1);
    lsum1 += __shfl_xor_sync(0xffffffffu, lsum1, 2);
    if (tg == 0) {
        g_bs[baseQ + m0 + g]     = mA + __logf(lsum0);
        g_bs[baseQ + m0 + g + 8] = mB + __logf(lsum1);
    }
    float inv0 = 1.f / lsum0, inv1 = 1.f / lsum1;
#pragma unroll
    for (int n = 0; n < 4; n++) {
        float2 v01 = make_float2(dacc[n*4+0]*inv0, dacc[n*4+1]*inv0);
        float2 v23 = make_float2(dacc[n*4+2]*inv1, dacc[n*4+3]*inv1);
        *(float2*)&g_ret[(size_t)(baseQ + m0 + g)*32 + n*8 + 2*tg]     = v01;
        *(float2*)&g_ret[(size_t)(baseQ + m0 + g + 8)*32 + n*8 + 2*tg] = v23;
    }
}

// ---------------- un-sort + cross-hash softmax + residual --------------------
__global__ void k_combine(const float* __restrict__ x, float* __restrict__ out) {
    __shared__ int   s_d[4][32];
    __shared__ float s_p[4][32];
    int tx = threadIdx.x, c = threadIdx.y;
    int l = blockIdx.x*32 + tx;
    if (c < 4) {
        int d = g_undo[c*L + l];
        s_d[c][tx] = d;
        s_p[c][tx] = g_bs[d];
    }
    __syncthreads();
    if (c == 0) {
        float b0 = s_p[0][tx], b1 = s_p[1][tx], b2 = s_p[2][tx], b3 = s_p[3][tx];
        float mm = fmaxf(fmaxf(b0,b1), fmaxf(b2,b3));
        float e0 = __expf(b0-mm), e1 = __expf(b1-mm), e2 = __expf(b2-mm), e3 = __expf(b3-mm);
        float inv = 1.f/(e0+e1+e2+e3);
        s_p[0][tx] = e0*inv; s_p[1][tx] = e1*inv; s_p[2][tx] = e2*inv; s_p[3][tx] = e3*inv;
    }
    __syncthreads();
    float sum = 0.f;
#pragma unroll
    for (int h = 0; h < 4; h++)
        sum += s_p[h][tx] * g_ret[(size_t)s_d[h][tx]*32 + c];
    out[c*L + l] = sum + x[c*L + l];
}

// ---------------- launcher ---------------------------------------------------
extern "C" void kernel_launch(void* const* d_in, const int* in_sizes, int n_in,
                              void* d_out, int out_size) {
    const float* x   = (const float*)d_in[0];
    const float* wm  = (const float*)d_in[1];
    const float* bm  = (const float*)d_in[2];
    const float* wa  = (const float*)d_in[3];
    const float* ba  = (const float*)d_in[4];
    const float* rot = (const float*)d_in[5];
    float* out = (float*)d_out;

    k_embed<<<L/128, 128>>>(x, wm, bm, wa, ba, rot);
    k_scanA<<<64, 256>>>();
    k_scatter<<<NTILES, 256>>>();
    k_attn<<<NHASH*NCHUNK, 288>>>();                 // 4th launch -> profiled
    k_combine<<<L/32, dim3(32,32)>>>(x, out);
}